// round 3
// baseline (speedup 1.0000x reference)
#include <cuda_runtime.h>

#define Bc     4
#define Nc     1024
#define Hc     8
#define Dc     64
#define DIMc   512
#define INNERc 512
#define QKV3c  1536
#define BHc    32
#define KKc    716
#define SCALEc 0.125f

#define DSTR   1028          // dots row stride (floats): %32==4 -> conflict-free frags
#define QSTR   68            // Q / K / V chunk row stride
#define SMEM_FLOATS (32 * DSTR + 32 * QSTR + 128 * QSTR)
#define SMEM_BYTES  (SMEM_FLOATS * 4 + 16 * 32 * 4 + 16 * 32 * 4 + 16 * 4)

// Scratch (device globals: no allocations allowed)
__device__ float g_qkv[Bc * Nc * QKV3c];          // [b*n][3*inner]
__device__ float g_att[Bc * Nc * INNERc];         // [b*n][h*d]

// ---------------------------------------------------------------------------
// helpers
// ---------------------------------------------------------------------------
__device__ __forceinline__ unsigned f2tf(float f) {
    unsigned r;
    asm("cvt.rna.tf32.f32 %0, %1;" : "=r"(r) : "f"(f));
    return r;
}
__device__ __forceinline__ void split_tf32(float v, float& hi, float& lo) {
    unsigned h = f2tf(v);
    float hf = __uint_as_float(h);
    hi = hf;
    lo = __uint_as_float(f2tf(v - hf));
}
__device__ __forceinline__ void mma8(float* c, const float* a, const float* b) {
    asm volatile(
        "mma.sync.aligned.m16n8k8.row.col.f32.tf32.tf32.f32 "
        "{%0,%1,%2,%3}, {%4,%5,%6,%7}, {%8,%9}, {%0,%1,%2,%3};"
        : "+f"(c[0]), "+f"(c[1]), "+f"(c[2]), "+f"(c[3])
        : "r"(__float_as_uint(a[0])), "r"(__float_as_uint(a[1])),
          "r"(__float_as_uint(a[2])), "r"(__float_as_uint(a[3])),
          "r"(__float_as_uint(b[0])), "r"(__float_as_uint(b[1])));
}
__device__ __forceinline__ unsigned f2o(float x) {
    unsigned u = __float_as_uint(x);
    return (u & 0x80000000u) ? ~u : (u | 0x80000000u);
}
__device__ __forceinline__ float o2f(unsigned u) {
    unsigned f = (u & 0x80000000u) ? (u & 0x7fffffffu) : ~u;
    return __uint_as_float(f);
}

// ---------------------------------------------------------------------------
// Fused kernel: dots = QK^T*s -> exact top-KK mask -> softmax -> P@V
// CTA: 32 query rows of one (b,h). 512 threads (16 warps). 179KB dyn smem.
// ---------------------------------------------------------------------------
__global__ __launch_bounds__(512, 1) void k_fused() {
    extern __shared__ float smem[];
    float* dots = smem;                          // [32][DSTR]
    float* sQ   = smem + 32 * DSTR;              // [32][QSTR]
    float* sKV  = sQ + 32 * QSTR;                // [128][QSTR]
    int*      hist = (int*)(sKV + 128 * QSTR);   // [16][32]
    unsigned* cand = (unsigned*)(hist + 16 * 32);// [16][32]
    int*      gc   = (int*)(cand + 16 * 32);     // [16]

    const int tid = threadIdx.x, lane = tid & 31, w = tid >> 5;
    const int tig = lane & 3, grp = lane >> 2;
    const int bh = blockIdx.y, b = bh >> 3, h = bh & 7;
    const int i0 = blockIdx.x * 32;
    const float* qg = g_qkv + (size_t)(b * Nc) * QKV3c + h * Dc;
    const float* kg = qg + INNERc;
    const float* vg = qg + 2 * INNERc;

    // ---- load Q block (32x64), fold in SCALE ----
    {
        int m = tid >> 4, d4 = tid & 15;
        float4 v = *(const float4*)&qg[(i0 + m) * QKV3c + d4 * 4];
        sQ[m * QSTR + d4 * 4 + 0] = v.x * SCALEc;
        sQ[m * QSTR + d4 * 4 + 1] = v.y * SCALEc;
        sQ[m * QSTR + d4 * 4 + 2] = v.z * SCALEc;
        sQ[m * QSTR + d4 * 4 + 3] = v.w * SCALEc;
    }

    const int wm = w & 1, wn = w >> 1;   // wm: m-tile, wn: 0..7

    // ================= Stage 1: dots = (Q*s) @ K^T =================
    for (int jc = 0; jc < 8; jc++) {
        __syncthreads();   // sKV free to overwrite (also covers sQ at jc=0 pre-load barrier below)
        // load K chunk [128 j][64 d] -> sKV[j][d]
#pragma unroll
        for (int l = 0; l < 4; l++) {
            int e = tid + l * 512;
            int j = e >> 4, d4 = e & 15;
            float4 v = *(const float4*)&kg[(size_t)(jc * 128 + j) * QKV3c + d4 * 4];
            sKV[j * QSTR + d4 * 4 + 0] = v.x;
            sKV[j * QSTR + d4 * 4 + 1] = v.y;
            sKV[j * QSTR + d4 * 4 + 2] = v.z;
            sKV[j * QSTR + d4 * 4 + 3] = v.w;
        }
        __syncthreads();

        float acc[2][4] = {};
#pragma unroll
        for (int kk = 0; kk < 64; kk += 8) {
            float ah[4], al[4];
            int mr = wm * 16 + grp;
            split_tf32(sQ[mr * QSTR + kk + tig],           ah[0], al[0]);
            split_tf32(sQ[(mr + 8) * QSTR + kk + tig],     ah[1], al[1]);
            split_tf32(sQ[mr * QSTR + kk + 4 + tig],       ah[2], al[2]);
            split_tf32(sQ[(mr + 8) * QSTR + kk + 4 + tig], ah[3], al[3]);
#pragma unroll
            for (int g = 0; g < 2; g++) {
                int jn = wn * 16 + g * 8 + grp;
                float bh2[2], bl2[2];
                split_tf32(sKV[jn * QSTR + kk + tig],     bh2[0], bl2[0]);
                split_tf32(sKV[jn * QSTR + kk + 4 + tig], bh2[1], bl2[1]);
                mma8(acc[g], ah, bh2);
                mma8(acc[g], ah, bl2);
                mma8(acc[g], al, bh2);
            }
        }
        // write dots tile
        int row = wm * 16 + grp;
#pragma unroll
        for (int g = 0; g < 2; g++) {
            int col = jc * 128 + wn * 16 + g * 8 + tig * 2;
            dots[row * DSTR + col]           = acc[g][0];
            dots[row * DSTR + col + 1]       = acc[g][1];
            dots[(row + 8) * DSTR + col]     = acc[g][2];
            dots[(row + 8) * DSTR + col + 1] = acc[g][3];
        }
    }
    __syncthreads();

    // ================= Stage 2: per-row top-KK + softmax (warp per row) ====
    const unsigned FULL = 0xffffffffu;
#pragma unroll 1
    for (int rr = 0; rr < 2; rr++) {
        int r_idx = w * 2 + rr;
        float* drow = dots + r_idx * DSTR;

        unsigned mn = 0xffffffffu, mx = 0u;
#pragma unroll
        for (int i = 0; i < 32; i++) {
            unsigned u = f2o(drow[i * 32 + lane]);
            mn = min(mn, u);
            mx = max(mx, u);
        }
#pragma unroll
        for (int o = 16; o; o >>= 1) {
            mn = min(mn, __shfl_xor_sync(FULL, mn, o));
            mx = max(mx, __shfl_xor_sync(FULL, mx, o));
        }

        unsigned long long lo = mn;
        unsigned long long range = (unsigned long long)mx - mn + 1ull;
        int r = Nc - KKc;   // 308
        unsigned thr = mn;

        for (int pass = 0; pass < 12; pass++) {
            if (range == 1ull) { thr = (unsigned)lo; break; }
            hist[w * 32 + lane] = 0;
            __syncwarp();
            unsigned lo32 = (unsigned)lo;
            unsigned hi32 = (unsigned)(lo + range - 1ull);
#pragma unroll
            for (int i = 0; i < 32; i++) {
                unsigned u = f2o(drow[i * 32 + lane]);
                if (u >= lo32 && u <= hi32) {
                    int bin = (int)(((unsigned long long)(u - lo32) * 32ull) / range);
                    atomicAdd(&hist[w * 32 + bin], 1);
                }
            }
            __syncwarp();
            int myh = hist[w * 32 + lane];
            int c = myh;
#pragma unroll
            for (int o = 1; o < 32; o <<= 1) {
                int t = __shfl_up_sync(FULL, c, o);
                if (lane >= o) c += t;
            }
            unsigned bal = __ballot_sync(FULL, c > r);
            int bkt = __ffs(bal) - 1;
            int prev = __shfl_sync(FULL, c - myh, bkt);
            int cnt  = __shfl_sync(FULL, myh, bkt);
            int r2   = r - prev;
            unsigned long long nlo = lo + ((unsigned long long)bkt * range + 31ull) / 32ull;
            unsigned long long nhi = lo + ((unsigned long long)(bkt + 1) * range + 31ull) / 32ull - 1ull;

            if (cnt <= 32) {
                if (lane == 0) gc[w] = 0;
                __syncwarp();
                unsigned glo = (unsigned)nlo, ghi = (unsigned)nhi;
#pragma unroll
                for (int i = 0; i < 32; i++) {
                    unsigned u = f2o(drow[i * 32 + lane]);
                    if (u >= glo && u <= ghi) {
                        int p = atomicAdd(&gc[w], 1);
                        cand[w * 32 + p] = u;
                    }
                }
                __syncwarp();
                unsigned tu = 0;
                int rk = -1;
                if (lane < cnt) {
                    tu = cand[w * 32 + lane];
                    rk = 0;
                    for (int j = 0; j < cnt; j++) {
                        unsigned o2 = cand[w * 32 + j];
                        rk += (o2 < tu) || (o2 == tu && j < lane);
                    }
                }
                unsigned who = __ballot_sync(FULL, rk == r2);
                thr = __shfl_sync(FULL, tu, __ffs(who) - 1);
                break;
            } else {
                lo = nlo;
                range = nhi - nlo + 1ull;
                r = r2;
            }
        }

        // masked softmax in place
        float rmax = o2f(mx);
        float sum = 0.f;
#pragma unroll
        for (int i = 0; i < 32; i++) {
            float v = drow[i * 32 + lane];
            unsigned u = f2o(v);
            float e = (u >= thr) ? __expf(v - rmax) : 0.f;
            drow[i * 32 + lane] = e;
            sum += e;
        }
#pragma unroll
        for (int o = 16; o; o >>= 1) sum += __shfl_xor_sync(FULL, sum, o);
        float inv = 1.0f / sum;
#pragma unroll
        for (int i = 0; i < 32; i++) drow[i * 32 + lane] *= inv;
    }

    // ================= Stage 3: out = P @ V =================
    float oacc[4] = {};
    for (int vc = 0; vc < 8; vc++) {
        __syncthreads();
        // load V chunk [128 j][64 d]
#pragma unroll
        for (int l = 0; l < 4; l++) {
            int e = tid + l * 512;
            int j = e >> 4, d4 = e & 15;
            float4 v = *(const float4*)&vg[(size_t)(vc * 128 + j) * QKV3c + d4 * 4];
            sKV[j * QSTR + d4 * 4 + 0] = v.x;
            sKV[j * QSTR + d4 * 4 + 1] = v.y;
            sKV[j * QSTR + d4 * 4 + 2] = v.z;
            sKV[j * QSTR + d4 * 4 + 3] = v.w;
        }
        __syncthreads();

#pragma unroll 4
        for (int kk = 0; kk < 128; kk += 8) {
            float ah[4], al[4];
            int mr = wm * 16 + grp;
            int kc = vc * 128 + kk;
            split_tf32(dots[mr * DSTR + kc + tig],           ah[0], al[0]);
            split_tf32(dots[(mr + 8) * DSTR + kc + tig],     ah[1], al[1]);
            split_tf32(dots[mr * DSTR + kc + 4 + tig],       ah[2], al[2]);
            split_tf32(dots[(mr + 8) * DSTR + kc + 4 + tig], ah[3], al[3]);
            float bh2[2], bl2[2];
            split_tf32(sKV[(kk + tig) * QSTR + wn * 8 + grp],     bh2[0], bl2[0]);
            split_tf32(sKV[(kk + 4 + tig) * QSTR + wn * 8 + grp], bh2[1], bl2[1]);
            mma8(oacc, ah, bh2);
            mma8(oacc, ah, bl2);
            mma8(oacc, al, bh2);
        }
    }
    // epilogue -> g_att
    {
        int row = b * Nc + i0 + wm * 16 + grp;
        int col = h * Dc + wn * 8 + tig * 2;
        *(float2*)&g_att[row * INNERc + col]       = make_float2(oacc[0], oacc[1]);
        *(float2*)&g_att[(row + 8) * INNERc + col] = make_float2(oacc[2], oacc[3]);
    }
}

// ---------------------------------------------------------------------------
// Kernel 1: qkv = x @ w_qkv   (4096 x 512) @ (512 x 1536), 3xTF32
// ---------------------------------------------------------------------------
__global__ __launch_bounds__(256) void k_qkv(const float* __restrict__ x,
                                             const float* __restrict__ w) {
    __shared__ float Ah[16][136], Al[16][136], Bh[16][136], Bl[16][136];
    const int tid = threadIdx.x, lane = tid & 31, wrp = tid >> 5;
    const int wm = wrp >> 1, wn = wrp & 1;
    const int tig = lane & 3, grp = lane >> 2;
    const int row0 = blockIdx.y * 128, col0 = blockIdx.x * 128;
    float acc[2][8][4] = {};

    for (int kt = 0; kt < DIMc; kt += 16) {
#pragma unroll
        for (int l = 0; l < 2; l++) {
            int idx = tid + l * 256;
            int m = idx >> 2, c4 = idx & 3;
            float4 v = *(const float4*)&x[(row0 + m) * DIMc + kt + c4 * 4];
            float vv[4] = {v.x, v.y, v.z, v.w};
#pragma unroll
            for (int i = 0; i < 4; i++)
                split_tf32(vv[i], Ah[c4 * 4 + i][m], Al[c4 * 4 + i][m]);
        }
#pragma unroll
        for (int l = 0; l < 2; l++) {
            int idx = tid + l * 256;
            int kr = idx >> 5, n4 = idx & 31;
            float4 v = *(const float4*)&w[(kt + kr) * QKV3c + col0 + n4 * 4];
            float vv[4] = {v.x, v.y, v.z, v.w};
#pragma unroll
            for (int i = 0; i < 4; i++)
                split_tf32(vv[i], Bh[kr][n4 * 4 + i], Bl[kr][n4 * 4 + i]);
        }
        __syncthreads();
#pragma unroll
        for (int kk = 0; kk < 16; kk += 8) {
            float ah[2][4], al[2][4];
#pragma unroll
            for (int f = 0; f < 2; f++) {
                int m = wm * 32 + f * 16 + grp;
                ah[f][0] = Ah[kk + tig][m];     al[f][0] = Al[kk + tig][m];
                ah[f][1] = Ah[kk + tig][m + 8]; al[f][1] = Al[kk + tig][m + 8];
                ah[f][2] = Ah[kk + 4 + tig][m]; al[f][2] = Al[kk + 4 + tig][m];
                ah[f][3] = Ah[kk + 4 + tig][m + 8];
                al[f][3] = Al[kk + 4 + tig][m + 8];
            }
#pragma unroll
            for (int g = 0; g < 8; g++) {
                int n = wn * 64 + g * 8 + grp;
                float bh2[2], bl2[2];
                bh2[0] = Bh[kk + tig][n]; bh2[1] = Bh[kk + 4 + tig][n];
                bl2[0] = Bl[kk + tig][n]; bl2[1] = Bl[kk + 4 + tig][n];
#pragma unroll
                for (int f = 0; f < 2; f++) {
                    mma8(acc[f][g], ah[f], bh2);
                    mma8(acc[f][g], ah[f], bl2);
                    mma8(acc[f][g], al[f], bh2);
                }
            }
        }
        __syncthreads();
    }
#pragma unroll
    for (int f = 0; f < 2; f++) {
        int row = row0 + wm * 32 + f * 16 + grp;
#pragma unroll
        for (int g = 0; g < 8; g++) {
            int col = col0 + wn * 64 + g * 8 + tig * 2;
            *(float2*)&g_qkv[row * QKV3c + col] = make_float2(acc[f][g][0], acc[f][g][1]);
            *(float2*)&g_qkv[(row + 8) * QKV3c + col] = make_float2(acc[f][g][2], acc[f][g][3]);
        }
    }
}

// ---------------------------------------------------------------------------
// Kernel 5: out = att @ w_out + b_out   (4096x512)@(512x512), 3xTF32
// ---------------------------------------------------------------------------
__global__ __launch_bounds__(256) void k_out(const float* __restrict__ w,
                                             const float* __restrict__ bias,
                                             float* __restrict__ out) {
    __shared__ float Ah[16][136], Al[16][136], Bh[16][136], Bl[16][136];
    const int tid = threadIdx.x, lane = tid & 31, wrp = tid >> 5;
    const int wm = wrp >> 1, wn = wrp & 1;
    const int tig = lane & 3, grp = lane >> 2;
    const int row0 = blockIdx.y * 128, col0 = blockIdx.x * 128;
    float acc[2][8][4] = {};

    for (int kt = 0; kt < INNERc; kt += 16) {
#pragma unroll
        for (int l = 0; l < 2; l++) {
            int idx = tid + l * 256;
            int m = idx >> 2, c4 = idx & 3;
            float4 v = *(const float4*)&g_att[(row0 + m) * INNERc + kt + c4 * 4];
            float vv[4] = {v.x, v.y, v.z, v.w};
#pragma unroll
            for (int i = 0; i < 4; i++)
                split_tf32(vv[i], Ah[c4 * 4 + i][m], Al[c4 * 4 + i][m]);
        }
#pragma unroll
        for (int l = 0; l < 2; l++) {
            int idx = tid + l * 256;
            int kr = idx >> 5, n4 = idx & 31;
            float4 v = *(const float4*)&w[(kt + kr) * DIMc + col0 + n4 * 4];
            float vv[4] = {v.x, v.y, v.z, v.w};
#pragma unroll
            for (int i = 0; i < 4; i++)
                split_tf32(vv[i], Bh[kr][n4 * 4 + i], Bl[kr][n4 * 4 + i]);
        }
        __syncthreads();
#pragma unroll
        for (int kk = 0; kk < 16; kk += 8) {
            float ah[2][4], al[2][4];
#pragma unroll
            for (int f = 0; f < 2; f++) {
                int m = wm * 32 + f * 16 + grp;
                ah[f][0] = Ah[kk + tig][m];     al[f][0] = Al[kk + tig][m];
                ah[f][1] = Ah[kk + tig][m + 8]; al[f][1] = Al[kk + tig][m + 8];
                ah[f][2] = Ah[kk + 4 + tig][m]; al[f][2] = Al[kk + 4 + tig][m];
                ah[f][3] = Ah[kk + 4 + tig][m + 8];
                al[f][3] = Al[kk + 4 + tig][m + 8];
            }
#pragma unroll
            for (int g = 0; g < 8; g++) {
                int n = wn * 64 + g * 8 + grp;
                float bh2[2], bl2[2];
                bh2[0] = Bh[kk + tig][n]; bh2[1] = Bh[kk + 4 + tig][n];
                bl2[0] = Bl[kk + tig][n]; bl2[1] = Bl[kk + 4 + tig][n];
#pragma unroll
                for (int f = 0; f < 2; f++) {
                    mma8(acc[f][g], ah[f], bh2);
                    mma8(acc[f][g], ah[f], bl2);
                    mma8(acc[f][g], al[f], bh2);
                }
            }
        }
        __syncthreads();
    }
#pragma unroll
    for (int f = 0; f < 2; f++) {
        int row = row0 + wm * 32 + f * 16 + grp;
#pragma unroll
        for (int g = 0; g < 8; g++) {
            int col = col0 + wn * 64 + g * 8 + tig * 2;
            float b0 = bias[col], b1 = bias[col + 1];
            *(float2*)&out[row * DIMc + col] =
                make_float2(acc[f][g][0] + b0, acc[f][g][1] + b1);
            *(float2*)&out[(row + 8) * DIMc + col] =
                make_float2(acc[f][g][2] + b0, acc[f][g][3] + b1);
        }
    }
}

// ---------------------------------------------------------------------------
extern "C" void kernel_launch(void* const* d_in, const int* in_sizes, int n_in,
                              void* d_out, int out_size) {
    const float* x     = (const float*)d_in[0];  // [4,1024,512]
    const float* w_qkv = (const float*)d_in[1];  // [512,1536]
    const float* w_out = (const float*)d_in[2];  // [512,512]
    const float* b_out = (const float*)d_in[3];  // [512]
    float* out = (float*)d_out;                  // [4,1024,512]

    cudaFuncSetAttribute(k_fused, cudaFuncAttributeMaxDynamicSharedMemorySize,
                         SMEM_BYTES);

    k_qkv<<<dim3(QKV3c / 128, (Bc * Nc) / 128), 256>>>(x, w_qkv);
    k_fused<<<dim3(Nc / 32, BHc), 512, SMEM_BYTES>>>();
    k_out<<<dim3(DIMc / 128, (Bc * Nc) / 128), 256>>>(w_out, b_out, out);
}

// round 4
// speedup vs baseline: 1.6547x; 1.6547x over previous
#include <cuda_runtime.h>

#define Bc     4
#define Nc     1024
#define Hc     8
#define Dc     64
#define DIMc   512
#define INNERc 512
#define QKV3c  1536
#define BHc    32
#define KKc    716
#define SCALEc 0.125f

// Scratch (device globals: no allocations allowed)
__device__ float g_qkv[Bc * Nc * QKV3c];          // [b*n][3*inner]
__device__ float g_dots[(size_t)BHc * Nc * Nc];   // [bh][i][j]
__device__ float g_att[Bc * Nc * INNERc];         // [b*n][h*d]

// ---------------------------------------------------------------------------
// helpers
// ---------------------------------------------------------------------------
__device__ __forceinline__ unsigned f2tf(float f) {
    unsigned r;
    asm("cvt.rna.tf32.f32 %0, %1;" : "=r"(r) : "f"(f));
    return r;
}
__device__ __forceinline__ void split_tf32(float v, float& hi, float& lo) {
    unsigned h = f2tf(v);
    float hf = __uint_as_float(h);
    hi = hf;
    lo = __uint_as_float(f2tf(v - hf));
}
__device__ __forceinline__ void mma8(float* c, const float* a, const float* b) {
    asm volatile(
        "mma.sync.aligned.m16n8k8.row.col.f32.tf32.tf32.f32 "
        "{%0,%1,%2,%3}, {%4,%5,%6,%7}, {%8,%9}, {%0,%1,%2,%3};"
        : "+f"(c[0]), "+f"(c[1]), "+f"(c[2]), "+f"(c[3])
        : "r"(__float_as_uint(a[0])), "r"(__float_as_uint(a[1])),
          "r"(__float_as_uint(a[2])), "r"(__float_as_uint(a[3])),
          "r"(__float_as_uint(b[0])), "r"(__float_as_uint(b[1])));
}
__device__ __forceinline__ unsigned f2o(float x) {
    unsigned u = __float_as_uint(x);
    return (u & 0x80000000u) ? ~u : (u | 0x80000000u);
}
__device__ __forceinline__ float o2f(unsigned u) {
    unsigned f = (u & 0x80000000u) ? (u & 0x7fffffffu) : ~u;
    return __uint_as_float(f);
}

// ---------------------------------------------------------------------------
// Kernel 1: qkv = x @ w_qkv   (4096 x 512) @ (512 x 1536), 3xTF32
// ---------------------------------------------------------------------------
__global__ __launch_bounds__(256) void k_qkv(const float* __restrict__ x,
                                             const float* __restrict__ w) {
    __shared__ float Ah[16][136], Al[16][136], Bh[16][136], Bl[16][136];
    const int tid = threadIdx.x, lane = tid & 31, wrp = tid >> 5;
    const int wm = wrp >> 1, wn = wrp & 1;
    const int tig = lane & 3, grp = lane >> 2;
    const int row0 = blockIdx.y * 128, col0 = blockIdx.x * 128;
    float acc[2][8][4] = {};

    for (int kt = 0; kt < DIMc; kt += 16) {
#pragma unroll
        for (int l = 0; l < 2; l++) {
            int idx = tid + l * 256;
            int m = idx >> 2, c4 = idx & 3;
            float4 v = *(const float4*)&x[(row0 + m) * DIMc + kt + c4 * 4];
            float vv[4] = {v.x, v.y, v.z, v.w};
#pragma unroll
            for (int i = 0; i < 4; i++)
                split_tf32(vv[i], Ah[c4 * 4 + i][m], Al[c4 * 4 + i][m]);
        }
#pragma unroll
        for (int l = 0; l < 2; l++) {
            int idx = tid + l * 256;
            int kr = idx >> 5, n4 = idx & 31;
            float4 v = *(const float4*)&w[(kt + kr) * QKV3c + col0 + n4 * 4];
            float vv[4] = {v.x, v.y, v.z, v.w};
#pragma unroll
            for (int i = 0; i < 4; i++)
                split_tf32(vv[i], Bh[kr][n4 * 4 + i], Bl[kr][n4 * 4 + i]);
        }
        __syncthreads();
#pragma unroll
        for (int kk = 0; kk < 16; kk += 8) {
            float ah[2][4], al[2][4];
#pragma unroll
            for (int f = 0; f < 2; f++) {
                int m = wm * 32 + f * 16 + grp;
                ah[f][0] = Ah[kk + tig][m];     al[f][0] = Al[kk + tig][m];
                ah[f][1] = Ah[kk + tig][m + 8]; al[f][1] = Al[kk + tig][m + 8];
                ah[f][2] = Ah[kk + 4 + tig][m]; al[f][2] = Al[kk + 4 + tig][m];
                ah[f][3] = Ah[kk + 4 + tig][m + 8];
                al[f][3] = Al[kk + 4 + tig][m + 8];
            }
#pragma unroll
            for (int g = 0; g < 8; g++) {
                int n = wn * 64 + g * 8 + grp;
                float bh2[2], bl2[2];
                bh2[0] = Bh[kk + tig][n]; bh2[1] = Bh[kk + 4 + tig][n];
                bl2[0] = Bl[kk + tig][n]; bl2[1] = Bl[kk + 4 + tig][n];
#pragma unroll
                for (int f = 0; f < 2; f++) {
                    mma8(acc[f][g], ah[f], bh2);
                    mma8(acc[f][g], ah[f], bl2);
                    mma8(acc[f][g], al[f], bh2);
                }
            }
        }
        __syncthreads();
    }
#pragma unroll
    for (int f = 0; f < 2; f++) {
        int row = row0 + wm * 32 + f * 16 + grp;
#pragma unroll
        for (int g = 0; g < 8; g++) {
            int col = col0 + wn * 64 + g * 8 + tig * 2;
            *(float2*)&g_qkv[row * QKV3c + col] = make_float2(acc[f][g][0], acc[f][g][1]);
            *(float2*)&g_qkv[(row + 8) * QKV3c + col] = make_float2(acc[f][g][2], acc[f][g][3]);
        }
    }
}

// ---------------------------------------------------------------------------
// Kernel 2: dots[bh] = (Q[bh] @ K[bh]^T) * scale, 3xTF32   (R2 version)
// ---------------------------------------------------------------------------
__global__ __launch_bounds__(256) void k_dots() {
    __shared__ float Ah[16][136], Al[16][136], Bh[16][136], Bl[16][136];
    const int tid = threadIdx.x, lane = tid & 31, wrp = tid >> 5;
    const int wm = wrp >> 1, wn = wrp & 1;
    const int tig = lane & 3, grp = lane >> 2;
    const int bh = blockIdx.z, b = bh >> 3, h = bh & 7;
    const int i0 = blockIdx.y * 128, j0 = blockIdx.x * 128;
    const float* qbase = g_qkv + (size_t)(b * Nc) * QKV3c + h * Dc;
    const float* kbase = g_qkv + (size_t)(b * Nc) * QKV3c + INNERc + h * Dc;
    float acc[2][8][4] = {};

    for (int kt = 0; kt < Dc; kt += 16) {
#pragma unroll
        for (int l = 0; l < 2; l++) {
            int idx = tid + l * 256;
            int m = idx >> 2, c4 = idx & 3;
            float4 v = *(const float4*)&qbase[(i0 + m) * QKV3c + kt + c4 * 4];
            float vv[4] = {v.x, v.y, v.z, v.w};
#pragma unroll
            for (int i = 0; i < 4; i++)
                split_tf32(vv[i], Ah[c4 * 4 + i][m], Al[c4 * 4 + i][m]);
        }
#pragma unroll
        for (int l = 0; l < 2; l++) {
            int idx = tid + l * 256;
            int m = idx >> 2, c4 = idx & 3;
            float4 v = *(const float4*)&kbase[(j0 + m) * QKV3c + kt + c4 * 4];
            float vv[4] = {v.x, v.y, v.z, v.w};
#pragma unroll
            for (int i = 0; i < 4; i++)
                split_tf32(vv[i], Bh[c4 * 4 + i][m], Bl[c4 * 4 + i][m]);
        }
        __syncthreads();
#pragma unroll
        for (int kk = 0; kk < 16; kk += 8) {
            float ah[2][4], al[2][4];
#pragma unroll
            for (int f = 0; f < 2; f++) {
                int m = wm * 32 + f * 16 + grp;
                ah[f][0] = Ah[kk + tig][m];     al[f][0] = Al[kk + tig][m];
                ah[f][1] = Ah[kk + tig][m + 8]; al[f][1] = Al[kk + tig][m + 8];
                ah[f][2] = Ah[kk + 4 + tig][m]; al[f][2] = Al[kk + 4 + tig][m];
                ah[f][3] = Ah[kk + 4 + tig][m + 8];
                al[f][3] = Al[kk + 4 + tig][m + 8];
            }
#pragma unroll
            for (int g = 0; g < 8; g++) {
                int n = wn * 64 + g * 8 + grp;
                float bh2[2], bl2[2];
                bh2[0] = Bh[kk + tig][n]; bh2[1] = Bh[kk + 4 + tig][n];
                bl2[0] = Bl[kk + tig][n]; bl2[1] = Bl[kk + 4 + tig][n];
#pragma unroll
                for (int f = 0; f < 2; f++) {
                    mma8(acc[f][g], ah[f], bh2);
                    mma8(acc[f][g], ah[f], bl2);
                    mma8(acc[f][g], al[f], bh2);
                }
            }
        }
        __syncthreads();
    }
    float* out = g_dots + (size_t)bh * Nc * Nc;
#pragma unroll
    for (int f = 0; f < 2; f++) {
        int row = i0 + wm * 32 + f * 16 + grp;
#pragma unroll
        for (int g = 0; g < 8; g++) {
            int col = j0 + wn * 64 + g * 8 + tig * 2;
            *(float2*)&out[(size_t)row * Nc + col] =
                make_float2(acc[f][g][0] * SCALEc, acc[f][g][1] * SCALEc);
            *(float2*)&out[(size_t)(row + 8) * Nc + col] =
                make_float2(acc[f][g][2] * SCALEc, acc[f][g][3] * SCALEc);
        }
    }
}

// ---------------------------------------------------------------------------
// Kernel 3: warp-per-row exact top-KK threshold + masked softmax (in place)
// 256 threads = 8 rows per block; row lives in 32 registers per lane.
// ---------------------------------------------------------------------------
__global__ __launch_bounds__(256) void k_topk() {
    __shared__ int      hist[8][32];
    __shared__ unsigned cand[8][32];
    __shared__ int      gc[8];

    const unsigned FULL = 0xffffffffu;
    const int tid = threadIdx.x, lane = tid & 31, w = tid >> 5;
    const size_t row = (size_t)blockIdx.x * 8 + w;
    float* base = g_dots + row * Nc;

    // load row: lane holds columns {c*128 + lane*4 .. +3} for c in 0..7
    unsigned u[32];
#pragma unroll
    for (int c = 0; c < 8; c++) {
        float4 v4 = *(const float4*)&base[c * 128 + lane * 4];
        u[c * 4 + 0] = f2o(v4.x);
        u[c * 4 + 1] = f2o(v4.y);
        u[c * 4 + 2] = f2o(v4.z);
        u[c * 4 + 3] = f2o(v4.w);
    }

    // warp min/max
    unsigned mn = u[0], mx = u[0];
#pragma unroll
    for (int i = 1; i < 32; i++) { mn = min(mn, u[i]); mx = max(mx, u[i]); }
#pragma unroll
    for (int o = 16; o; o >>= 1) {
        mn = min(mn, __shfl_xor_sync(FULL, mn, o));
        mx = max(mx, __shfl_xor_sync(FULL, mx, o));
    }

    unsigned long long lo = mn;
    unsigned long long range = (unsigned long long)mx - mn + 1ull;
    int r = Nc - KKc;   // 308 (0-based ascending rank of the threshold)
    unsigned thr = mn;

    for (int pass = 0; pass < 10; pass++) {
        if (range == 1ull) { thr = (unsigned)lo; break; }
        hist[w][lane] = 0;
        __syncwarp();
        const unsigned lo32 = (unsigned)lo;
        const unsigned hi32 = (unsigned)(lo + range - 1ull);
        const bool small = (range <= 32ull);
        const unsigned mul = small ? 0u : (unsigned)((32ull << 32) / range);
#pragma unroll
        for (int i = 0; i < 32; i++) {
            if (u[i] >= lo32 && u[i] <= hi32) {
                unsigned d = u[i] - lo32;
                int bin = small ? (int)d : (int)__umulhi(d, mul);
                atomicAdd(&hist[w][bin], 1);
            }
        }
        __syncwarp();
        int myh = hist[w][lane];
        int c = myh;
#pragma unroll
        for (int o = 1; o < 32; o <<= 1) {
            int t = __shfl_up_sync(FULL, c, o);
            if (lane >= o) c += t;
        }
        unsigned bal = __ballot_sync(FULL, c > r);
        int bkt  = __ffs(bal) - 1;
        int prev = __shfl_sync(FULL, c - myh, bkt);
        int cnt  = __shfl_sync(FULL, myh, bkt);
        int r2   = r - prev;

        unsigned long long nlo, nhi;
        if (small) {
            nlo = lo + (unsigned)bkt;
            nhi = nlo;
        } else {
            unsigned long long dl = (((unsigned long long)bkt << 32) + mul - 1ull) / mul;
            unsigned long long dh = ((((unsigned long long)(bkt + 1)) << 32) + mul - 1ull) / mul - 1ull;
            if (dh > range - 1ull) dh = range - 1ull;
            nlo = lo + dl;
            nhi = lo + dh;
        }

        if (cnt <= 32) {
            if (lane == 0) gc[w] = 0;
            __syncwarp();
            const unsigned glo = (unsigned)nlo, ghi = (unsigned)nhi;
#pragma unroll
            for (int i = 0; i < 32; i++) {
                if (u[i] >= glo && u[i] <= ghi) {
                    int p = atomicAdd(&gc[w], 1);
                    cand[w][p] = u[i];
                }
            }
            __syncwarp();
            unsigned tu = 0;
            int rk = -1;
            if (lane < cnt) {
                tu = cand[w][lane];
                rk = 0;
                for (int j = 0; j < cnt; j++) {
                    unsigned o2 = cand[w][j];
                    rk += (o2 < tu) || (o2 == tu && j < lane);
                }
            }
            unsigned who = __ballot_sync(FULL, rk == r2);
            thr = __shfl_sync(FULL, tu, __ffs(who) - 1);
            break;
        } else {
            lo = nlo;
            range = nhi - nlo + 1ull;
            r = r2;
        }
    }

    // masked softmax in place (overwrite key regs with exp values)
    const float rmax = o2f(mx);
    float sum = 0.f;
#pragma unroll
    for (int i = 0; i < 32; i++) {
        unsigned ui = u[i];
        float v = o2f(ui);
        float e = (ui >= thr) ? __expf(v - rmax) : 0.f;
        u[i] = __float_as_uint(e);
        sum += e;
    }
#pragma unroll
    for (int o = 16; o; o >>= 1) sum += __shfl_xor_sync(FULL, sum, o);
    const float inv = 1.0f / sum;
#pragma unroll
    for (int c = 0; c < 8; c++) {
        float4 o4 = make_float4(__uint_as_float(u[c * 4 + 0]) * inv,
                                __uint_as_float(u[c * 4 + 1]) * inv,
                                __uint_as_float(u[c * 4 + 2]) * inv,
                                __uint_as_float(u[c * 4 + 3]) * inv);
        *(float4*)&base[c * 128 + lane * 4] = o4;
    }
}

// ---------------------------------------------------------------------------
// Kernel 4: att[bh] = P[bh] @ V[bh]   (1024x1024)@(1024x64), 3xTF32 (R2)
// ---------------------------------------------------------------------------
__global__ __launch_bounds__(256) void k_av() {
    __shared__ float Ah[16][136], Al[16][136], Bh[16][72], Bl[16][72];
    const int tid = threadIdx.x, lane = tid & 31, wrp = tid >> 5;
    const int wm = wrp >> 1, wn = wrp & 1;
    const int tig = lane & 3, grp = lane >> 2;
    const int bh = blockIdx.y, b = bh >> 3, h = bh & 7;
    const int i0 = blockIdx.x * 128;
    const float* P = g_dots + (size_t)bh * Nc * Nc;
    const float* vbase = g_qkv + (size_t)(b * Nc) * QKV3c + 2 * INNERc + h * Dc;
    float acc[2][4][4] = {};

    for (int kt = 0; kt < Nc; kt += 16) {
#pragma unroll
        for (int l = 0; l < 2; l++) {
            int idx = tid + l * 256;
            int m = idx >> 2, c4 = idx & 3;
            float4 v = *(const float4*)&P[(size_t)(i0 + m) * Nc + kt + c4 * 4];
            float vv[4] = {v.x, v.y, v.z, v.w};
#pragma unroll
            for (int i = 0; i < 4; i++)
                split_tf32(vv[i], Ah[c4 * 4 + i][m], Al[c4 * 4 + i][m]);
        }
        {
            int kr = tid >> 4, n4 = tid & 15;
            float4 v = *(const float4*)&vbase[(kt + kr) * QKV3c + n4 * 4];
            float vv[4] = {v.x, v.y, v.z, v.w};
#pragma unroll
            for (int i = 0; i < 4; i++)
                split_tf32(vv[i], Bh[kr][n4 * 4 + i], Bl[kr][n4 * 4 + i]);
        }
        __syncthreads();
#pragma unroll
        for (int kk = 0; kk < 16; kk += 8) {
            float ah[2][4], al[2][4];
#pragma unroll
            for (int f = 0; f < 2; f++) {
                int m = wm * 32 + f * 16 + grp;
                ah[f][0] = Ah[kk + tig][m];     al[f][0] = Al[kk + tig][m];
                ah[f][1] = Ah[kk + tig][m + 8]; al[f][1] = Al[kk + tig][m + 8];
                ah[f][2] = Ah[kk + 4 + tig][m]; al[f][2] = Al[kk + 4 + tig][m];
                ah[f][3] = Ah[kk + 4 + tig][m + 8];
                al[f][3] = Al[kk + 4 + tig][m + 8];
            }
#pragma unroll
            for (int g = 0; g < 4; g++) {
                int n = wn * 32 + g * 8 + grp;
                float bh2[2], bl2[2];
                bh2[0] = Bh[kk + tig][n]; bh2[1] = Bh[kk + 4 + tig][n];
                bl2[0] = Bl[kk + tig][n]; bl2[1] = Bl[kk + 4 + tig][n];
#pragma unroll
                for (int f = 0; f < 2; f++) {
                    mma8(acc[f][g], ah[f], bh2);
                    mma8(acc[f][g], ah[f], bl2);
                    mma8(acc[f][g], al[f], bh2);
                }
            }
        }
        __syncthreads();
    }
#pragma unroll
    for (int f = 0; f < 2; f++) {
        int rr = b * Nc + i0 + wm * 32 + f * 16 + grp;
#pragma unroll
        for (int g = 0; g < 4; g++) {
            int col = h * Dc + wn * 32 + g * 8 + tig * 2;
            *(float2*)&g_att[rr * INNERc + col] = make_float2(acc[f][g][0], acc[f][g][1]);
            *(float2*)&g_att[(rr + 8) * INNERc + col] = make_float2(acc[f][g][2], acc[f][g][3]);
        }
    }
}

// ---------------------------------------------------------------------------
// Kernel 5: out = att @ w_out + b_out   (4096x512)@(512x512), 3xTF32
// ---------------------------------------------------------------------------
__global__ __launch_bounds__(256) void k_out(const float* __restrict__ w,
                                             const float* __restrict__ bias,
                                             float* __restrict__ out) {
    __shared__ float Ah[16][136], Al[16][136], Bh[16][136], Bl[16][136];
    const int tid = threadIdx.x, lane = tid & 31, wrp = tid >> 5;
    const int wm = wrp >> 1, wn = wrp & 1;
    const int tig = lane & 3, grp = lane >> 2;
    const int row0 = blockIdx.y * 128, col0 = blockIdx.x * 128;
    float acc[2][8][4] = {};

    for (int kt = 0; kt < INNERc; kt += 16) {
#pragma unroll
        for (int l = 0; l < 2; l++) {
            int idx = tid + l * 256;
            int m = idx >> 2, c4 = idx & 3;
            float4 v = *(const float4*)&g_att[(row0 + m) * INNERc + kt + c4 * 4];
            float vv[4] = {v.x, v.y, v.z, v.w};
#pragma unroll
            for (int i = 0; i < 4; i++)
                split_tf32(vv[i], Ah[c4 * 4 + i][m], Al[c4 * 4 + i][m]);
        }
#pragma unroll
        for (int l = 0; l < 2; l++) {
            int idx = tid + l * 256;
            int kr = idx >> 5, n4 = idx & 31;
            float4 v = *(const float4*)&w[(kt + kr) * DIMc + col0 + n4 * 4];
            float vv[4] = {v.x, v.y, v.z, v.w};
#pragma unroll
            for (int i = 0; i < 4; i++)
                split_tf32(vv[i], Bh[kr][n4 * 4 + i], Bl[kr][n4 * 4 + i]);
        }
        __syncthreads();
#pragma unroll
        for (int kk = 0; kk < 16; kk += 8) {
            float ah[2][4], al[2][4];
#pragma unroll
            for (int f = 0; f < 2; f++) {
                int m = wm * 32 + f * 16 + grp;
                ah[f][0] = Ah[kk + tig][m];     al[f][0] = Al[kk + tig][m];
                ah[f][1] = Ah[kk + tig][m + 8]; al[f][1] = Al[kk + tig][m + 8];
                ah[f][2] = Ah[kk + 4 + tig][m]; al[f][2] = Al[kk + 4 + tig][m];
                ah[f][3] = Ah[kk + 4 + tig][m + 8];
                al[f][3] = Al[kk + 4 + tig][m + 8];
            }
#pragma unroll
            for (int g = 0; g < 8; g++) {
                int n = wn * 64 + g * 8 + grp;
                float bh2[2], bl2[2];
                bh2[0] = Bh[kk + tig][n]; bh2[1] = Bh[kk + 4 + tig][n];
                bl2[0] = Bl[kk + tig][n]; bl2[1] = Bl[kk + 4 + tig][n];
#pragma unroll
                for (int f = 0; f < 2; f++) {
                    mma8(acc[f][g], ah[f], bh2);
                    mma8(acc[f][g], ah[f], bl2);
                    mma8(acc[f][g], al[f], bh2);
                }
            }
        }
        __syncthreads();
    }
#pragma unroll
    for (int f = 0; f < 2; f++) {
        int row = row0 + wm * 32 + f * 16 + grp;
#pragma unroll
        for (int g = 0; g < 8; g++) {
            int col = col0 + wn * 64 + g * 8 + tig * 2;
            float b0 = bias[col], b1 = bias[col + 1];
            *(float2*)&out[row * DIMc + col] =
                make_float2(acc[f][g][0] + b0, acc[f][g][1] + b1);
            *(float2*)&out[(row + 8) * DIMc + col] =
                make_float2(acc[f][g][2] + b0, acc[f][g][3] + b1);
        }
    }
}

// ---------------------------------------------------------------------------
extern "C" void kernel_launch(void* const* d_in, const int* in_sizes, int n_in,
                              void* d_out, int out_size) {
    const float* x     = (const float*)d_in[0];  // [4,1024,512]
    const float* w_qkv = (const float*)d_in[1];  // [512,1536]
    const float* w_out = (const float*)d_in[2];  // [512,512]
    const float* b_out = (const float*)d_in[3];  // [512]
    float* out = (float*)d_out;                  // [4,1024,512]

    k_qkv<<<dim3(QKV3c / 128, (Bc * Nc) / 128), 256>>>(x, w_qkv);
    k_dots<<<dim3(Nc / 128, Nc / 128, BHc), 256>>>();
    k_topk<<<(BHc * Nc) / 8, 256>>>();
    k_av<<<dim3(Nc / 128, BHc), 256>>>();
    k_out<<<dim3(DIMc / 128, (Bc * Nc) / 128), 256>>>(w_out, b_out, out);
}

// round 5
// speedup vs baseline: 2.0198x; 1.2207x over previous
#include <cuda_runtime.h>
#include <cuda_fp16.h>

#define Bc     4
#define Nc     1024
#define Hc     8
#define Dc     64
#define DIMc   512
#define INNERc 512
#define QKV3c  1536
#define BHc    32
#define KKc    716
#define SCALEc 0.125f

// Scratch (device globals: no allocations allowed)
__device__ float  g_qkv[Bc * Nc * QKV3c];          // [b*n][3*inner] fp32
__device__ float  g_dots[(size_t)BHc * Nc * Nc];   // [bh][i][j] fp32 (pre-softmax)
__device__ __half g_p[(size_t)BHc * Nc * Nc];      // [bh][i][j] fp16 (post-softmax)
__device__ __half g_att[Bc * Nc * INNERc];         // [b*n][h*d] fp16

// ---------------------------------------------------------------------------
// helpers
// ---------------------------------------------------------------------------
__device__ __forceinline__ unsigned f2tf(float f) {
    unsigned r;
    asm("cvt.rna.tf32.f32 %0, %1;" : "=r"(r) : "f"(f));
    return r;
}
__device__ __forceinline__ void split_tf32(float v, float& hi, float& lo) {
    unsigned h = f2tf(v);
    float hf = __uint_as_float(h);
    hi = hf;
    lo = __uint_as_float(f2tf(v - hf));
}
__device__ __forceinline__ void mma8(float* c, const float* a, const float* b) {
    asm volatile(
        "mma.sync.aligned.m16n8k8.row.col.f32.tf32.tf32.f32 "
        "{%0,%1,%2,%3}, {%4,%5,%6,%7}, {%8,%9}, {%0,%1,%2,%3};"
        : "+f"(c[0]), "+f"(c[1]), "+f"(c[2]), "+f"(c[3])
        : "r"(__float_as_uint(a[0])), "r"(__float_as_uint(a[1])),
          "r"(__float_as_uint(a[2])), "r"(__float_as_uint(a[3])),
          "r"(__float_as_uint(b[0])), "r"(__float_as_uint(b[1])));
}
__device__ __forceinline__ void mma16(float* c, const unsigned* a,
                                      unsigned b0, unsigned b1) {
    asm volatile(
        "mma.sync.aligned.m16n8k16.row.col.f32.f16.f16.f32 "
        "{%0,%1,%2,%3}, {%4,%5,%6,%7}, {%8,%9}, {%0,%1,%2,%3};"
        : "+f"(c[0]), "+f"(c[1]), "+f"(c[2]), "+f"(c[3])
        : "r"(a[0]), "r"(a[1]), "r"(a[2]), "r"(a[3]), "r"(b0), "r"(b1));
}
__device__ __forceinline__ unsigned f2o(float x) {
    unsigned u = __float_as_uint(x);
    return (u & 0x80000000u) ? ~u : (u | 0x80000000u);
}
__device__ __forceinline__ float o2f(unsigned u) {
    unsigned f = (u & 0x80000000u) ? (u & 0x7fffffffu) : ~u;
    return __uint_as_float(f);
}

// ---------------------------------------------------------------------------
// Kernel 1: qkv = x @ w_qkv   (4096 x 512) @ (512 x 1536), 3xTF32
// ---------------------------------------------------------------------------
__global__ __launch_bounds__(256) void k_qkv(const float* __restrict__ x,
                                             const float* __restrict__ w) {
    __shared__ float Ah[16][136], Al[16][136], Bh[16][136], Bl[16][136];
    const int tid = threadIdx.x, lane = tid & 31, wrp = tid >> 5;
    const int wm = wrp >> 1, wn = wrp & 1;
    const int tig = lane & 3, grp = lane >> 2;
    const int row0 = blockIdx.y * 128, col0 = blockIdx.x * 128;
    float acc[2][8][4] = {};

    for (int kt = 0; kt < DIMc; kt += 16) {
#pragma unroll
        for (int l = 0; l < 2; l++) {
            int idx = tid + l * 256;
            int m = idx >> 2, c4 = idx & 3;
            float4 v = *(const float4*)&x[(row0 + m) * DIMc + kt + c4 * 4];
            float vv[4] = {v.x, v.y, v.z, v.w};
#pragma unroll
            for (int i = 0; i < 4; i++)
                split_tf32(vv[i], Ah[c4 * 4 + i][m], Al[c4 * 4 + i][m]);
        }
#pragma unroll
        for (int l = 0; l < 2; l++) {
            int idx = tid + l * 256;
            int kr = idx >> 5, n4 = idx & 31;
            float4 v = *(const float4*)&w[(kt + kr) * QKV3c + col0 + n4 * 4];
            float vv[4] = {v.x, v.y, v.z, v.w};
#pragma unroll
            for (int i = 0; i < 4; i++)
                split_tf32(vv[i], Bh[kr][n4 * 4 + i], Bl[kr][n4 * 4 + i]);
        }
        __syncthreads();
#pragma unroll
        for (int kk = 0; kk < 16; kk += 8) {
            float ah[2][4], al[2][4];
#pragma unroll
            for (int f = 0; f < 2; f++) {
                int m = wm * 32 + f * 16 + grp;
                ah[f][0] = Ah[kk + tig][m];     al[f][0] = Al[kk + tig][m];
                ah[f][1] = Ah[kk + tig][m + 8]; al[f][1] = Al[kk + tig][m + 8];
                ah[f][2] = Ah[kk + 4 + tig][m]; al[f][2] = Al[kk + 4 + tig][m];
                ah[f][3] = Ah[kk + 4 + tig][m + 8];
                al[f][3] = Al[kk + 4 + tig][m + 8];
            }
#pragma unroll
            for (int g = 0; g < 8; g++) {
                int n = wn * 64 + g * 8 + grp;
                float bh2[2], bl2[2];
                bh2[0] = Bh[kk + tig][n]; bh2[1] = Bh[kk + 4 + tig][n];
                bl2[0] = Bl[kk + tig][n]; bl2[1] = Bl[kk + 4 + tig][n];
#pragma unroll
                for (int f = 0; f < 2; f++) {
                    mma8(acc[f][g], ah[f], bh2);
                    mma8(acc[f][g], ah[f], bl2);
                    mma8(acc[f][g], al[f], bh2);
                }
            }
        }
        __syncthreads();
    }
#pragma unroll
    for (int f = 0; f < 2; f++) {
        int row = row0 + wm * 32 + f * 16 + grp;
#pragma unroll
        for (int g = 0; g < 8; g++) {
            int col = col0 + wn * 64 + g * 8 + tig * 2;
            *(float2*)&g_qkv[row * QKV3c + col] = make_float2(acc[f][g][0], acc[f][g][1]);
            *(float2*)&g_qkv[(row + 8) * QKV3c + col] = make_float2(acc[f][g][2], acc[f][g][3]);
        }
    }
}

// ---------------------------------------------------------------------------
// Kernel 2: dots[bh] = (Q[bh] @ K[bh]^T) * scale, 3xTF32
// ---------------------------------------------------------------------------
__global__ __launch_bounds__(256) void k_dots() {
    __shared__ float Ah[16][136], Al[16][136], Bh[16][136], Bl[16][136];
    const int tid = threadIdx.x, lane = tid & 31, wrp = tid >> 5;
    const int wm = wrp >> 1, wn = wrp & 1;
    const int tig = lane & 3, grp = lane >> 2;
    const int bh = blockIdx.z, b = bh >> 3, h = bh & 7;
    const int i0 = blockIdx.y * 128, j0 = blockIdx.x * 128;
    const float* qbase = g_qkv + (size_t)(b * Nc) * QKV3c + h * Dc;
    const float* kbase = g_qkv + (size_t)(b * Nc) * QKV3c + INNERc + h * Dc;
    float acc[2][8][4] = {};

    for (int kt = 0; kt < Dc; kt += 16) {
#pragma unroll
        for (int l = 0; l < 2; l++) {
            int idx = tid + l * 256;
            int m = idx >> 2, c4 = idx & 3;
            float4 v = *(const float4*)&qbase[(i0 + m) * QKV3c + kt + c4 * 4];
            float vv[4] = {v.x, v.y, v.z, v.w};
#pragma unroll
            for (int i = 0; i < 4; i++)
                split_tf32(vv[i], Ah[c4 * 4 + i][m], Al[c4 * 4 + i][m]);
        }
#pragma unroll
        for (int l = 0; l < 2; l++) {
            int idx = tid + l * 256;
            int m = idx >> 2, c4 = idx & 3;
            float4 v = *(const float4*)&kbase[(j0 + m) * QKV3c + kt + c4 * 4];
            float vv[4] = {v.x, v.y, v.z, v.w};
#pragma unroll
            for (int i = 0; i < 4; i++)
                split_tf32(vv[i], Bh[c4 * 4 + i][m], Bl[c4 * 4 + i][m]);
        }
        __syncthreads();
#pragma unroll
        for (int kk = 0; kk < 16; kk += 8) {
            float ah[2][4], al[2][4];
#pragma unroll
            for (int f = 0; f < 2; f++) {
                int m = wm * 32 + f * 16 + grp;
                ah[f][0] = Ah[kk + tig][m];     al[f][0] = Al[kk + tig][m];
                ah[f][1] = Ah[kk + tig][m + 8]; al[f][1] = Al[kk + tig][m + 8];
                ah[f][2] = Ah[kk + 4 + tig][m]; al[f][2] = Al[kk + 4 + tig][m];
                ah[f][3] = Ah[kk + 4 + tig][m + 8];
                al[f][3] = Al[kk + 4 + tig][m + 8];
            }
#pragma unroll
            for (int g = 0; g < 8; g++) {
                int n = wn * 64 + g * 8 + grp;
                float bh2[2], bl2[2];
                bh2[0] = Bh[kk + tig][n]; bh2[1] = Bh[kk + 4 + tig][n];
                bl2[0] = Bl[kk + tig][n]; bl2[1] = Bl[kk + 4 + tig][n];
#pragma unroll
                for (int f = 0; f < 2; f++) {
                    mma8(acc[f][g], ah[f], bh2);
                    mma8(acc[f][g], ah[f], bl2);
                    mma8(acc[f][g], al[f], bh2);
                }
            }
        }
        __syncthreads();
    }
    float* out = g_dots + (size_t)bh * Nc * Nc;
#pragma unroll
    for (int f = 0; f < 2; f++) {
        int row = i0 + wm * 32 + f * 16 + grp;
#pragma unroll
        for (int g = 0; g < 8; g++) {
            int col = j0 + wn * 64 + g * 8 + tig * 2;
            *(float2*)&out[(size_t)row * Nc + col] =
                make_float2(acc[f][g][0] * SCALEc, acc[f][g][1] * SCALEc);
            *(float2*)&out[(size_t)(row + 8) * Nc + col] =
                make_float2(acc[f][g][2] * SCALEc, acc[f][g][3] * SCALEc);
        }
    }
}

// ---------------------------------------------------------------------------
// Kernel 3: warp-per-row exact top-KK threshold + masked softmax
// reads g_dots (fp32), writes g_p (fp16)
// ---------------------------------------------------------------------------
__global__ __launch_bounds__(256) void k_topk() {
    __shared__ int      hist[8][32];
    __shared__ unsigned cand[8][32];
    __shared__ int      gc[8];

    const unsigned FULL = 0xffffffffu;
    const int tid = threadIdx.x, lane = tid & 31, w = tid >> 5;
    const size_t row = (size_t)blockIdx.x * 8 + w;
    const float* base = g_dots + row * Nc;
    __half* pb = g_p + row * Nc;

    unsigned u[32];
#pragma unroll
    for (int c = 0; c < 8; c++) {
        float4 v4 = *(const float4*)&base[c * 128 + lane * 4];
        u[c * 4 + 0] = f2o(v4.x);
        u[c * 4 + 1] = f2o(v4.y);
        u[c * 4 + 2] = f2o(v4.z);
        u[c * 4 + 3] = f2o(v4.w);
    }

    unsigned mn = u[0], mx = u[0];
#pragma unroll
    for (int i = 1; i < 32; i++) { mn = min(mn, u[i]); mx = max(mx, u[i]); }
#pragma unroll
    for (int o = 16; o; o >>= 1) {
        mn = min(mn, __shfl_xor_sync(FULL, mn, o));
        mx = max(mx, __shfl_xor_sync(FULL, mx, o));
    }

    unsigned long long lo = mn;
    unsigned long long range = (unsigned long long)mx - mn + 1ull;
    int r = Nc - KKc;   // 308
    unsigned thr = mn;

    for (int pass = 0; pass < 10; pass++) {
        if (range == 1ull) { thr = (unsigned)lo; break; }
        hist[w][lane] = 0;
        __syncwarp();
        const unsigned lo32 = (unsigned)lo;
        const unsigned hi32 = (unsigned)(lo + range - 1ull);
        const bool small = (range <= 32ull);
        const unsigned mul = small ? 0u : (unsigned)((32ull << 32) / range);
#pragma unroll
        for (int i = 0; i < 32; i++) {
            if (u[i] >= lo32 && u[i] <= hi32) {
                unsigned d = u[i] - lo32;
                int bin = small ? (int)d : (int)__umulhi(d, mul);
                atomicAdd(&hist[w][bin], 1);
            }
        }
        __syncwarp();
        int myh = hist[w][lane];
        int c = myh;
#pragma unroll
        for (int o = 1; o < 32; o <<= 1) {
            int t = __shfl_up_sync(FULL, c, o);
            if (lane >= o) c += t;
        }
        unsigned bal = __ballot_sync(FULL, c > r);
        int bkt  = __ffs(bal) - 1;
        int prev = __shfl_sync(FULL, c - myh, bkt);
        int cnt  = __shfl_sync(FULL, myh, bkt);
        int r2   = r - prev;

        unsigned long long nlo, nhi;
        if (small) {
            nlo = lo + (unsigned)bkt;
            nhi = nlo;
        } else {
            unsigned long long dl = (((unsigned long long)bkt << 32) + mul - 1ull) / mul;
            unsigned long long dh = ((((unsigned long long)(bkt + 1)) << 32) + mul - 1ull) / mul - 1ull;
            if (dh > range - 1ull) dh = range - 1ull;
            nlo = lo + dl;
            nhi = lo + dh;
        }

        if (cnt <= 32) {
            if (lane == 0) gc[w] = 0;
            __syncwarp();
            const unsigned glo = (unsigned)nlo, ghi = (unsigned)nhi;
#pragma unroll
            for (int i = 0; i < 32; i++) {
                if (u[i] >= glo && u[i] <= ghi) {
                    int p = atomicAdd(&gc[w], 1);
                    cand[w][p] = u[i];
                }
            }
            __syncwarp();
            unsigned tu = 0;
            int rk = -1;
            if (lane < cnt) {
                tu = cand[w][lane];
                rk = 0;
                for (int j = 0; j < cnt; j++) {
                    unsigned o2 = cand[w][j];
                    rk += (o2 < tu) || (o2 == tu && j < lane);
                }
            }
            unsigned who = __ballot_sync(FULL, rk == r2);
            thr = __shfl_sync(FULL, tu, __ffs(who) - 1);
            break;
        } else {
            lo = nlo;
            range = nhi - nlo + 1ull;
            r = r2;
        }
    }

    // masked softmax; write fp16 P
    const float rmax = o2f(mx);
    float sum = 0.f;
    float e[32];
#pragma unroll
    for (int i = 0; i < 32; i++) {
        unsigned ui = u[i];
        float v = o2f(ui);
        e[i] = (ui >= thr) ? __expf(v - rmax) : 0.f;
        sum += e[i];
    }
#pragma unroll
    for (int o = 16; o; o >>= 1) sum += __shfl_xor_sync(FULL, sum, o);
    const float inv = 1.0f / sum;
#pragma unroll
    for (int c = 0; c < 8; c++) {
        __half2 h01 = __floats2half2_rn(e[c * 4 + 0] * inv, e[c * 4 + 1] * inv);
        __half2 h23 = __floats2half2_rn(e[c * 4 + 2] * inv, e[c * 4 + 3] * inv);
        uint2 pk;
        pk.x = *(unsigned*)&h01;
        pk.y = *(unsigned*)&h23;
        *(uint2*)&pb[c * 128 + lane * 4] = pk;
    }
}

// ---------------------------------------------------------------------------
// Kernel 4: att[bh] = P[bh] @ V[bh]  fp16 MMA (m16n8k16), P fp16, V cvt fp16
// block: 128 rows x 64 cols (full D), BK=64, 8 warps (4m x 2n), warp 32x32
// ---------------------------------------------------------------------------
__global__ __launch_bounds__(256) void k_av() {
    __shared__ __half Ph[128][72];
    __shared__ __half Vt[64][72];     // V transposed: [n][k]
    const int tid = threadIdx.x, lane = tid & 31, wrp = tid >> 5;
    const int wm = wrp >> 1, wn = wrp & 1;
    const int tig = lane & 3, grp = lane >> 2;
    const int bh = blockIdx.y, b = bh >> 3, h = bh & 7;
    const int i0 = blockIdx.x * 128;
    const __half* pg = g_p + ((size_t)bh * Nc + i0) * Nc;
    const float* vbase = g_qkv + (size_t)(b * Nc) * QKV3c + 2 * INNERc + h * Dc;
    float acc[2][4][4] = {};

    for (int kc = 0; kc < Nc; kc += 64) {
        __syncthreads();
        // P tile: 128 rows x 64 halves
#pragma unroll
        for (int l = 0; l < 4; l++) {
            int idx = tid + l * 256;
            int row = idx >> 3, c8 = idx & 7;
            *(int4*)&Ph[row][c8 * 8] =
                *(const int4*)&pg[(size_t)row * Nc + kc + c8 * 8];
        }
        // V tile transposed: [64 n][64 k]
#pragma unroll
        for (int l = 0; l < 4; l++) {
            int idx = tid + l * 256;
            int k = idx >> 4, n4 = idx & 15;
            float4 v = *(const float4*)&vbase[(size_t)(kc + k) * QKV3c + n4 * 4];
            Vt[n4 * 4 + 0][k] = __float2half(v.x);
            Vt[n4 * 4 + 1][k] = __float2half(v.y);
            Vt[n4 * 4 + 2][k] = __float2half(v.z);
            Vt[n4 * 4 + 3][k] = __float2half(v.w);
        }
        __syncthreads();

#pragma unroll
        for (int kk = 0; kk < 64; kk += 16) {
            unsigned a[2][4];
#pragma unroll
            for (int f = 0; f < 2; f++) {
                int m = wm * 32 + f * 16 + grp;
                a[f][0] = *(const unsigned*)&Ph[m][kk + tig * 2];
                a[f][1] = *(const unsigned*)&Ph[m + 8][kk + tig * 2];
                a[f][2] = *(const unsigned*)&Ph[m][kk + tig * 2 + 8];
                a[f][3] = *(const unsigned*)&Ph[m + 8][kk + tig * 2 + 8];
            }
#pragma unroll
            for (int g = 0; g < 4; g++) {
                int n = wn * 32 + g * 8 + grp;
                unsigned b0 = *(const unsigned*)&Vt[n][kk + tig * 2];
                unsigned b1 = *(const unsigned*)&Vt[n][kk + tig * 2 + 8];
#pragma unroll
                for (int f = 0; f < 2; f++) mma16(acc[f][g], a[f], b0, b1);
            }
        }
    }
    // epilogue -> g_att (fp16)
#pragma unroll
    for (int f = 0; f < 2; f++) {
        int rr = b * Nc + i0 + wm * 32 + f * 16 + grp;
#pragma unroll
        for (int g = 0; g < 4; g++) {
            int col = h * Dc + wn * 32 + g * 8 + tig * 2;
            __half2 h0 = __floats2half2_rn(acc[f][g][0], acc[f][g][1]);
            __half2 h1 = __floats2half2_rn(acc[f][g][2], acc[f][g][3]);
            *(__half2*)&g_att[rr * INNERc + col] = h0;
            *(__half2*)&g_att[(rr + 8) * INNERc + col] = h1;
        }
    }
}

// ---------------------------------------------------------------------------
// Kernel 5: out = att @ w_out + b_out  fp16 MMA
// block 128x128, BK=64, 8 warps (2m x 4n), warp 64x32
// ---------------------------------------------------------------------------
__global__ __launch_bounds__(256) void k_out(const float* __restrict__ w,
                                             const float* __restrict__ bias,
                                             float* __restrict__ out) {
    __shared__ __half Ah[128][72];
    __shared__ __half Bt[128][72];    // w_out transposed: [n][k]
    const int tid = threadIdx.x, lane = tid & 31, wrp = tid >> 5;
    const int wm = wrp & 1, wn = wrp >> 1;
    const int tig = lane & 3, grp = lane >> 2;
    const int row0 = blockIdx.y * 128, col0 = blockIdx.x * 128;
    float acc[4][4][4] = {};

    for (int kc = 0; kc < INNERc; kc += 64) {
        __syncthreads();
        // A tile: att rows (fp16 direct copy)
#pragma unroll
        for (int l = 0; l < 4; l++) {
            int idx = tid + l * 256;
            int row = idx >> 3, c8 = idx & 7;
            *(int4*)&Ah[row][c8 * 8] =
                *(const int4*)&g_att[(size_t)(row0 + row) * INNERc + kc + c8 * 8];
        }
        // B tile transposed: [128 n][64 k], cvt fp32->fp16
#pragma unroll
        for (int l = 0; l < 8; l++) {
            int idx = tid + l * 256;
            int k = idx >> 5, n4 = idx & 31;
            float4 v = *(const float4*)&w[(size_t)(kc + k) * DIMc + col0 + n4 * 4];
            Bt[n4 * 4 + 0][k] = __float2half(v.x);
            Bt[n4 * 4 + 1][k] = __float2half(v.y);
            Bt[n4 * 4 + 2][k] = __float2half(v.z);
            Bt[n4 * 4 + 3][k] = __float2half(v.w);
        }
        __syncthreads();

#pragma unroll
        for (int kk = 0; kk < 64; kk += 16) {
            unsigned a[4][4];
#pragma unroll
            for (int f = 0; f < 4; f++) {
                int m = wm * 64 + f * 16 + grp;
                a[f][0] = *(const unsigned*)&Ah[m][kk + tig * 2];
                a[f][1] = *(const unsigned*)&Ah[m + 8][kk + tig * 2];
                a[f][2] = *(const unsigned*)&Ah[m][kk + tig * 2 + 8];
                a[f][3] = *(const unsigned*)&Ah[m + 8][kk + tig * 2 + 8];
            }
#pragma unroll
            for (int g = 0; g < 4; g++) {
                int n = wn * 32 + g * 8 + grp;
                unsigned b0 = *(const unsigned*)&Bt[n][kk + tig * 2];
                unsigned b1 = *(const unsigned*)&Bt[n][kk + tig * 2 + 8];
#pragma unroll
                for (int f = 0; f < 4; f++) mma16(acc[f][g], a[f], b0, b1);
            }
        }
    }
#pragma unroll
    for (int f = 0; f < 4; f++) {
        int row = row0 + wm * 64 + f * 16 + grp;
#pragma unroll
        for (int g = 0; g < 4; g++) {
            int col = col0 + wn * 32 + g * 8 + tig * 2;
            float b0 = bias[col], b1 = bias[col + 1];
            *(float2*)&out[(size_t)row * DIMc + col] =
                make_float2(acc[f][g][0] + b0, acc[f][g][1] + b1);
            *(float2*)&out[(size_t)(row + 8) * DIMc + col] =
                make_float2(acc[f][g][2] + b0, acc[f][g][3] + b1);
        }
    }
}

// ---------------------------------------------------------------------------
extern "C" void kernel_launch(void* const* d_in, const int* in_sizes, int n_in,
                              void* d_out, int out_size) {
    const float* x     = (const float*)d_in[0];  // [4,1024,512]
    const float* w_qkv = (const float*)d_in[1];  // [512,1536]
    const float* w_out = (const float*)d_in[2];  // [512,512]
    const float* b_out = (const float*)d_in[3];  // [512]
    float* out = (float*)d_out;                  // [4,1024,512]

    k_qkv<<<dim3(QKV3c / 128, (Bc * Nc) / 128), 256>>>(x, w_qkv);
    k_dots<<<dim3(Nc / 128, Nc / 128, BHc), 256>>>();
    k_topk<<<(BHc * Nc) / 8, 256>>>();
    k_av<<<dim3(Nc / 128, BHc), 256>>>();
    k_out<<<dim3(DIMc / 128, (Bc * Nc) / 128), 256>>>(w_out, b_out, out);
}

// round 6
// speedup vs baseline: 2.7540x; 1.3635x over previous
#include <cuda_runtime.h>
#include <cuda_fp16.h>

#define Bc     4
#define Nc     1024
#define Hc     8
#define Dc     64
#define DIMc   512
#define INNERc 512
#define QKV3c  1536
#define BHc    32
#define KKc    716
#define SCALEc 0.125f

// Scratch (device globals: no allocations allowed)
__device__ float  g_qkv[Bc * Nc * QKV3c];          // [b*n][3*inner] fp32
__device__ float  g_dots[(size_t)BHc * Nc * Nc];   // [bh][i][j] fp32 (pre-softmax)
__device__ __half g_p[(size_t)BHc * Nc * Nc];      // [bh][i][j] fp16 (post-softmax)
__device__ __half g_att[Bc * Nc * INNERc];         // [b*n][h*d] fp16

// ---------------------------------------------------------------------------
// helpers
// ---------------------------------------------------------------------------
__device__ __forceinline__ void split_h(float v, __half& hi, __half& lo) {
    __half h = __float2half_rn(v);
    hi = h;
    lo = __float2half_rn(v - __half2float(h));
}
__device__ __forceinline__ void mma16(float* c, const unsigned* a,
                                      unsigned b0, unsigned b1) {
    asm volatile(
        "mma.sync.aligned.m16n8k16.row.col.f32.f16.f16.f32 "
        "{%0,%1,%2,%3}, {%4,%5,%6,%7}, {%8,%9}, {%0,%1,%2,%3};"
        : "+f"(c[0]), "+f"(c[1]), "+f"(c[2]), "+f"(c[3])
        : "r"(a[0]), "r"(a[1]), "r"(a[2]), "r"(a[3]), "r"(b0), "r"(b1));
}
__device__ __forceinline__ unsigned f2o(float x) {
    unsigned u = __float_as_uint(x);
    return (u & 0x80000000u) ? ~u : (u | 0x80000000u);
}
__device__ __forceinline__ float o2f(unsigned u) {
    unsigned f = (u & 0x80000000u) ? (u & 0x7fffffffu) : ~u;
    return __uint_as_float(f);
}

// ---------------------------------------------------------------------------
// Kernel 1: qkv = x @ w_qkv  (4096x512)@(512x1536), fp16-split (3 products)
// block 128x128, BK=32, 8 warps (2m x 4n), warp 64x32
// ---------------------------------------------------------------------------
__global__ __launch_bounds__(256) void k_qkv(const float* __restrict__ x,
                                             const float* __restrict__ w) {
    __shared__ __half Ah[128][40], Al[128][40];   // [m][k]
    __shared__ __half Bh[128][40], Bl[128][40];   // [n][k]
    const int tid = threadIdx.x, lane = tid & 31, wrp = tid >> 5;
    const int wm = wrp & 1, wn = wrp >> 1;
    const int tig = lane & 3, grp = lane >> 2;
    const int row0 = blockIdx.y * 128, col0 = blockIdx.x * 128;
    float acc[4][4][4] = {};

    const int am = tid >> 1, akp = tid & 1;       // A: row m, k-half
    const int bn = tid & 127, bkp = tid >> 7;     // B: col n, k-half

    for (int kt = 0; kt < DIMc; kt += 32) {
        __syncthreads();
        // A tile: 128m x 32k fp32 -> split halves [m][k]
#pragma unroll
        for (int c = 0; c < 4; c++) {
            float4 v = *(const float4*)&x[(row0 + am) * DIMc + kt + akp * 16 + c * 4];
            float vv[4] = {v.x, v.y, v.z, v.w};
            __half hh[4], ll[4];
#pragma unroll
            for (int i = 0; i < 4; i++) split_h(vv[i], hh[i], ll[i]);
            *(uint2*)&Ah[am][akp * 16 + c * 4] = *(uint2*)hh;
            *(uint2*)&Al[am][akp * 16 + c * 4] = *(uint2*)ll;
        }
        // B tile: w[k][n] -> [n][k] halves (transpose)
#pragma unroll
        for (int j = 0; j < 8; j++) {
            int k = bkp * 16 + j * 2;
            float v0 = w[(size_t)(kt + k) * QKV3c + col0 + bn];
            float v1 = w[(size_t)(kt + k + 1) * QKV3c + col0 + bn];
            __half h0, l0, h1, l1;
            split_h(v0, h0, l0);
            split_h(v1, h1, l1);
            *(__half2*)&Bh[bn][k] = __halves2half2(h0, h1);
            *(__half2*)&Bl[bn][k] = __halves2half2(l0, l1);
        }
        __syncthreads();

#pragma unroll
        for (int kk = 0; kk < 32; kk += 16) {
            unsigned ah[4][4], al[4][4];
#pragma unroll
            for (int f = 0; f < 4; f++) {
                int m = wm * 64 + f * 16 + grp;
                ah[f][0] = *(const unsigned*)&Ah[m][kk + tig * 2];
                ah[f][1] = *(const unsigned*)&Ah[m + 8][kk + tig * 2];
                ah[f][2] = *(const unsigned*)&Ah[m][kk + tig * 2 + 8];
                ah[f][3] = *(const unsigned*)&Ah[m + 8][kk + tig * 2 + 8];
                al[f][0] = *(const unsigned*)&Al[m][kk + tig * 2];
                al[f][1] = *(const unsigned*)&Al[m + 8][kk + tig * 2];
                al[f][2] = *(const unsigned*)&Al[m][kk + tig * 2 + 8];
                al[f][3] = *(const unsigned*)&Al[m + 8][kk + tig * 2 + 8];
            }
#pragma unroll
            for (int g = 0; g < 4; g++) {
                int n = wn * 32 + g * 8 + grp;
                unsigned bh0 = *(const unsigned*)&Bh[n][kk + tig * 2];
                unsigned bh1 = *(const unsigned*)&Bh[n][kk + tig * 2 + 8];
                unsigned bl0 = *(const unsigned*)&Bl[n][kk + tig * 2];
                unsigned bl1 = *(const unsigned*)&Bl[n][kk + tig * 2 + 8];
#pragma unroll
                for (int f = 0; f < 4; f++) {
                    mma16(acc[f][g], ah[f], bh0, bh1);
                    mma16(acc[f][g], ah[f], bl0, bl1);
                    mma16(acc[f][g], al[f], bh0, bh1);
                }
            }
        }
    }
#pragma unroll
    for (int f = 0; f < 4; f++) {
        int row = row0 + wm * 64 + f * 16 + grp;
#pragma unroll
        for (int g = 0; g < 4; g++) {
            int col = col0 + wn * 32 + g * 8 + tig * 2;
            *(float2*)&g_qkv[(size_t)row * QKV3c + col] =
                make_float2(acc[f][g][0], acc[f][g][1]);
            *(float2*)&g_qkv[(size_t)(row + 8) * QKV3c + col] =
                make_float2(acc[f][g][2], acc[f][g][3]);
        }
    }
}

// ---------------------------------------------------------------------------
// Kernel 2: dots[bh] = (Q*scale) @ K^T, fp16-split (3 products)
// block 128x128, D=64 in 2 BK=32 iters, 8 warps (2m x 4n)
// ---------------------------------------------------------------------------
__global__ __launch_bounds__(256) void k_dots() {
    __shared__ __half Qh[128][40], Ql[128][40];   // [m][k]
    __shared__ __half Kh[128][40], Kl[128][40];   // [n][k]
    const int tid = threadIdx.x, lane = tid & 31, wrp = tid >> 5;
    const int wm = wrp & 1, wn = wrp >> 1;
    const int tig = lane & 3, grp = lane >> 2;
    const int bh = blockIdx.z, b = bh >> 3, h = bh & 7;
    const int i0 = blockIdx.y * 128, j0 = blockIdx.x * 128;
    const float* qbase = g_qkv + (size_t)(b * Nc) * QKV3c + h * Dc;
    const float* kbase = g_qkv + (size_t)(b * Nc) * QKV3c + INNERc + h * Dc;
    float acc[4][4][4] = {};

    const int am = tid >> 1, akp = tid & 1;

    for (int kt = 0; kt < Dc; kt += 32) {
        __syncthreads();
        // Q tile (scale folded in)
#pragma unroll
        for (int c = 0; c < 4; c++) {
            float4 v = *(const float4*)&qbase[(size_t)(i0 + am) * QKV3c + kt + akp * 16 + c * 4];
            float vv[4] = {v.x * SCALEc, v.y * SCALEc, v.z * SCALEc, v.w * SCALEc};
            __half hh[4], ll[4];
#pragma unroll
            for (int i = 0; i < 4; i++) split_h(vv[i], hh[i], ll[i]);
            *(uint2*)&Qh[am][akp * 16 + c * 4] = *(uint2*)hh;
            *(uint2*)&Ql[am][akp * 16 + c * 4] = *(uint2*)ll;
        }
        // K tile
#pragma unroll
        for (int c = 0; c < 4; c++) {
            float4 v = *(const float4*)&kbase[(size_t)(j0 + am) * QKV3c + kt + akp * 16 + c * 4];
            float vv[4] = {v.x, v.y, v.z, v.w};
            __half hh[4], ll[4];
#pragma unroll
            for (int i = 0; i < 4; i++) split_h(vv[i], hh[i], ll[i]);
            *(uint2*)&Kh[am][akp * 16 + c * 4] = *(uint2*)hh;
            *(uint2*)&Kl[am][akp * 16 + c * 4] = *(uint2*)ll;
        }
        __syncthreads();

#pragma unroll
        for (int kk = 0; kk < 32; kk += 16) {
            unsigned ah[4][4], al[4][4];
#pragma unroll
            for (int f = 0; f < 4; f++) {
                int m = wm * 64 + f * 16 + grp;
                ah[f][0] = *(const unsigned*)&Qh[m][kk + tig * 2];
                ah[f][1] = *(const unsigned*)&Qh[m + 8][kk + tig * 2];
                ah[f][2] = *(const unsigned*)&Qh[m][kk + tig * 2 + 8];
                ah[f][3] = *(const unsigned*)&Qh[m + 8][kk + tig * 2 + 8];
                al[f][0] = *(const unsigned*)&Ql[m][kk + tig * 2];
                al[f][1] = *(const unsigned*)&Ql[m + 8][kk + tig * 2];
                al[f][2] = *(const unsigned*)&Ql[m][kk + tig * 2 + 8];
                al[f][3] = *(const unsigned*)&Ql[m + 8][kk + tig * 2 + 8];
            }
#pragma unroll
            for (int g = 0; g < 4; g++) {
                int n = wn * 32 + g * 8 + grp;
                unsigned bh0 = *(const unsigned*)&Kh[n][kk + tig * 2];
                unsigned bh1 = *(const unsigned*)&Kh[n][kk + tig * 2 + 8];
                unsigned bl0 = *(const unsigned*)&Kl[n][kk + tig * 2];
                unsigned bl1 = *(const unsigned*)&Kl[n][kk + tig * 2 + 8];
#pragma unroll
                for (int f = 0; f < 4; f++) {
                    mma16(acc[f][g], ah[f], bh0, bh1);
                    mma16(acc[f][g], ah[f], bl0, bl1);
                    mma16(acc[f][g], al[f], bh0, bh1);
                }
            }
        }
    }
    float* out = g_dots + (size_t)bh * Nc * Nc;
#pragma unroll
    for (int f = 0; f < 4; f++) {
        int row = i0 + wm * 64 + f * 16 + grp;
#pragma unroll
        for (int g = 0; g < 4; g++) {
            int col = j0 + wn * 32 + g * 8 + tig * 2;
            *(float2*)&out[(size_t)row * Nc + col] =
                make_float2(acc[f][g][0], acc[f][g][1]);
            *(float2*)&out[(size_t)(row + 8) * Nc + col] =
                make_float2(acc[f][g][2], acc[f][g][3]);
        }
    }
}

// ---------------------------------------------------------------------------
// Kernel 3: warp-per-row exact top-KK + masked softmax; 256-bin radix pass
// reads g_dots (fp32), writes g_p (fp16)
// ---------------------------------------------------------------------------
__global__ __launch_bounds__(256) void k_topk() {
    __shared__ int      hist[8][256];
    __shared__ unsigned cand[8][32];
    __shared__ int      gc[8];

    const unsigned FULL = 0xffffffffu;
    const int tid = threadIdx.x, lane = tid & 31, w = tid >> 5;
    const size_t row = (size_t)blockIdx.x * 8 + w;
    const float* base = g_dots + row * Nc;
    __half* pb = g_p + row * Nc;

    unsigned u[32];
#pragma unroll
    for (int c = 0; c < 8; c++) {
        float4 v4 = *(const float4*)&base[c * 128 + lane * 4];
        u[c * 4 + 0] = f2o(v4.x);
        u[c * 4 + 1] = f2o(v4.y);
        u[c * 4 + 2] = f2o(v4.z);
        u[c * 4 + 3] = f2o(v4.w);
    }

    unsigned mn = u[0], mx = u[0];
#pragma unroll
    for (int i = 1; i < 32; i++) { mn = min(mn, u[i]); mx = max(mx, u[i]); }
#pragma unroll
    for (int o = 16; o; o >>= 1) {
        mn = min(mn, __shfl_xor_sync(FULL, mn, o));
        mx = max(mx, __shfl_xor_sync(FULL, mx, o));
    }

    unsigned long long lo = mn;
    unsigned long long range = (unsigned long long)mx - mn + 1ull;
    int r = Nc - KKc;   // 308
    unsigned thr = mn;

    for (int pass = 0; pass < 6; pass++) {
        if (range == 1ull) { thr = (unsigned)lo; break; }
#pragma unroll
        for (int j = 0; j < 8; j++) hist[w][j * 32 + lane] = 0;
        __syncwarp();
        const unsigned lo32 = (unsigned)lo;
        const unsigned hi32 = (unsigned)(lo + range - 1ull);
        const bool small = (range <= 256ull);
        const unsigned mul = small ? 0u : (unsigned)((256ull << 32) / range);
#pragma unroll
        for (int i = 0; i < 32; i++) {
            if (u[i] >= lo32 && u[i] <= hi32) {
                unsigned d = u[i] - lo32;
                int bin = small ? (int)d : (int)__umulhi(d, mul);
                atomicAdd(&hist[w][bin], 1);
            }
        }
        __syncwarp();
        // scan over 256 bins: lane owns bins [8*lane, 8*lane+8)
        int loc[8], s = 0;
#pragma unroll
        for (int j = 0; j < 8; j++) { loc[j] = hist[w][lane * 8 + j]; s += loc[j]; }
        int c = s;
#pragma unroll
        for (int o = 1; o < 32; o <<= 1) {
            int t = __shfl_up_sync(FULL, c, o);
            if (lane >= o) c += t;
        }
        int excl = c - s;
        unsigned bal = __ballot_sync(FULL, c > r);
        int L = __ffs(bal) - 1;
        int bkt = 0, r2 = 0, cnt = 0;
        if (lane == L) {
            int a2 = excl;
#pragma unroll
            for (int j = 0; j < 8; j++) {
                if (a2 + loc[j] > r) { bkt = lane * 8 + j; r2 = r - a2; cnt = loc[j]; break; }
                a2 += loc[j];
            }
        }
        bkt = __shfl_sync(FULL, bkt, L);
        r2  = __shfl_sync(FULL, r2, L);
        cnt = __shfl_sync(FULL, cnt, L);

        unsigned long long nlo, nhi;
        if (small) {
            nlo = lo + (unsigned)bkt;
            nhi = nlo;
        } else {
            unsigned long long dl = (((unsigned long long)bkt << 32) + mul - 1ull) / mul;
            unsigned long long dh = ((((unsigned long long)(bkt + 1)) << 32) + mul - 1ull) / mul - 1ull;
            if (dh > range - 1ull) dh = range - 1ull;
            nlo = lo + dl;
            nhi = lo + dh;
        }

        if (cnt <= 32) {
            if (lane == 0) gc[w] = 0;
            __syncwarp();
            const unsigned glo = (unsigned)nlo, ghi = (unsigned)nhi;
#pragma unroll
            for (int i = 0; i < 32; i++) {
                if (u[i] >= glo && u[i] <= ghi) {
                    int p = atomicAdd(&gc[w], 1);
                    cand[w][p] = u[i];
                }
            }
            __syncwarp();
            unsigned tu = 0;
            int rk = -1;
            if (lane < cnt) {
                tu = cand[w][lane];
                rk = 0;
                for (int j = 0; j < cnt; j++) {
                    unsigned o2 = cand[w][j];
                    rk += (o2 < tu) || (o2 == tu && j < lane);
                }
            }
            unsigned who = __ballot_sync(FULL, rk == r2);
            thr = __shfl_sync(FULL, tu, __ffs(who) - 1);
            break;
        } else {
            lo = nlo;
            range = nhi - nlo + 1ull;
            r = r2;
        }
    }

    // masked softmax; write fp16 P
    const float rmax = o2f(mx);
    float sum = 0.f;
    float e[32];
#pragma unroll
    for (int i = 0; i < 32; i++) {
        unsigned ui = u[i];
        float v = o2f(ui);
        e[i] = (ui >= thr) ? __expf(v - rmax) : 0.f;
        sum += e[i];
    }
#pragma unroll
    for (int o = 16; o; o >>= 1) sum += __shfl_xor_sync(FULL, sum, o);
    const float inv = 1.0f / sum;
#pragma unroll
    for (int c = 0; c < 8; c++) {
        __half2 h01 = __floats2half2_rn(e[c * 4 + 0] * inv, e[c * 4 + 1] * inv);
        __half2 h23 = __floats2half2_rn(e[c * 4 + 2] * inv, e[c * 4 + 3] * inv);
        uint2 pk;
        pk.x = *(unsigned*)&h01;
        pk.y = *(unsigned*)&h23;
        *(uint2*)&pb[c * 128 + lane * 4] = pk;
    }
}

// ---------------------------------------------------------------------------
// Kernel 4: att[bh] = P[bh] @ V[bh]  fp16 MMA (m16n8k16)
// ---------------------------------------------------------------------------
__global__ __launch_bounds__(256) void k_av() {
    __shared__ __half Ph[128][72];
    __shared__ __half Vt[64][72];     // V transposed: [n][k]
    const int tid = threadIdx.x, lane = tid & 31, wrp = tid >> 5;
    const int wm = wrp >> 1, wn = wrp & 1;
    const int tig = lane & 3, grp = lane >> 2;
    const int bh = blockIdx.y, b = bh >> 3, h = bh & 7;
    const int i0 = blockIdx.x * 128;
    const __half* pg = g_p + ((size_t)bh * Nc + i0) * Nc;
    const float* vbase = g_qkv + (size_t)(b * Nc) * QKV3c + 2 * INNERc + h * Dc;
    float acc[2][4][4] = {};

    for (int kc = 0; kc < Nc; kc += 64) {
        __syncthreads();
#pragma unroll
        for (int l = 0; l < 4; l++) {
            int idx = tid + l * 256;
            int row = idx >> 3, c8 = idx & 7;
            *(int4*)&Ph[row][c8 * 8] =
                *(const int4*)&pg[(size_t)row * Nc + kc + c8 * 8];
        }
#pragma unroll
        for (int l = 0; l < 4; l++) {
            int idx = tid + l * 256;
            int k = idx >> 4, n4 = idx & 15;
            float4 v = *(const float4*)&vbase[(size_t)(kc + k) * QKV3c + n4 * 4];
            Vt[n4 * 4 + 0][k] = __float2half(v.x);
            Vt[n4 * 4 + 1][k] = __float2half(v.y);
            Vt[n4 * 4 + 2][k] = __float2half(v.z);
            Vt[n4 * 4 + 3][k] = __float2half(v.w);
        }
        __syncthreads();

#pragma unroll
        for (int kk = 0; kk < 64; kk += 16) {
            unsigned a[2][4];
#pragma unroll
            for (int f = 0; f < 2; f++) {
                int m = wm * 32 + f * 16 + grp;
                a[f][0] = *(const unsigned*)&Ph[m][kk + tig * 2];
                a[f][1] = *(const unsigned*)&Ph[m + 8][kk + tig * 2];
                a[f][2] = *(const unsigned*)&Ph[m][kk + tig * 2 + 8];
                a[f][3] = *(const unsigned*)&Ph[m + 8][kk + tig * 2 + 8];
            }
#pragma unroll
            for (int g = 0; g < 4; g++) {
                int n = wn * 32 + g * 8 + grp;
                unsigned b0 = *(const unsigned*)&Vt[n][kk + tig * 2];
                unsigned b1 = *(const unsigned*)&Vt[n][kk + tig * 2 + 8];
#pragma unroll
                for (int f = 0; f < 2; f++) mma16(acc[f][g], a[f], b0, b1);
            }
        }
    }
#pragma unroll
    for (int f = 0; f < 2; f++) {
        int rr = b * Nc + i0 + wm * 32 + f * 16 + grp;
#pragma unroll
        for (int g = 0; g < 4; g++) {
            int col = h * Dc + wn * 32 + g * 8 + tig * 2;
            __half2 h0 = __floats2half2_rn(acc[f][g][0], acc[f][g][1]);
            __half2 h1 = __floats2half2_rn(acc[f][g][2], acc[f][g][3]);
            *(__half2*)&g_att[rr * INNERc + col] = h0;
            *(__half2*)&g_att[(rr + 8) * INNERc + col] = h1;
        }
    }
}

// ---------------------------------------------------------------------------
// Kernel 5: out = att @ w_out + b_out  fp16 MMA
// ---------------------------------------------------------------------------
__global__ __launch_bounds__(256) void k_out(const float* __restrict__ w,
                                             const float* __restrict__ bias,
                                             float* __restrict__ out) {
    __shared__ __half Ah[128][72];
    __shared__ __half Bt[128][72];    // w_out transposed: [n][k]
    const int tid = threadIdx.x, lane = tid & 31, wrp = tid >> 5;
    const int wm = wrp & 1, wn = wrp >> 1;
    const int tig = lane & 3, grp = lane >> 2;
    const int row0 = blockIdx.y * 128, col0 = blockIdx.x * 128;
    float acc[4][4][4] = {};

    for (int kc = 0; kc < INNERc; kc += 64) {
        __syncthreads();
#pragma unroll
        for (int l = 0; l < 4; l++) {
            int idx = tid + l * 256;
            int row = idx >> 3, c8 = idx & 7;
            *(int4*)&Ah[row][c8 * 8] =
                *(const int4*)&g_att[(size_t)(row0 + row) * INNERc + kc + c8 * 8];
        }
#pragma unroll
        for (int l = 0; l < 8; l++) {
            int idx = tid + l * 256;
            int k = idx >> 5, n4 = idx & 31;
            float4 v = *(const float4*)&w[(size_t)(kc + k) * DIMc + col0 + n4 * 4];
            Bt[n4 * 4 + 0][k] = __float2half(v.x);
            Bt[n4 * 4 + 1][k] = __float2half(v.y);
            Bt[n4 * 4 + 2][k] = __float2half(v.z);
            Bt[n4 * 4 + 3][k] = __float2half(v.w);
        }
        __syncthreads();

#pragma unroll
        for (int kk = 0; kk < 64; kk += 16) {
            unsigned a[4][4];
#pragma unroll
            for (int f = 0; f < 4; f++) {
                int m = wm * 64 + f * 16 + grp;
                a[f][0] = *(const unsigned*)&Ah[m][kk + tig * 2];
                a[f][1] = *(const unsigned*)&Ah[m + 8][kk + tig * 2];
                a[f][2] = *(const unsigned*)&Ah[m][kk + tig * 2 + 8];
                a[f][3] = *(const unsigned*)&Ah[m + 8][kk + tig * 2 + 8];
            }
#pragma unroll
            for (int g = 0; g < 4; g++) {
                int n = wn * 32 + g * 8 + grp;
                unsigned b0 = *(const unsigned*)&Bt[n][kk + tig * 2];
                unsigned b1 = *(const unsigned*)&Bt[n][kk + tig * 2 + 8];
#pragma unroll
                for (int f = 0; f < 4; f++) mma16(acc[f][g], a[f], b0, b1);
            }
        }
    }
#pragma unroll
    for (int f = 0; f < 4; f++) {
        int row = row0 + wm * 64 + f * 16 + grp;
#pragma unroll
        for (int g = 0; g < 4; g++) {
            int col = col0 + wn * 32 + g * 8 + tig * 2;
            float b0 = bias[col], b1 = bias[col + 1];
            *(float2*)&out[(size_t)row * DIMc + col] =
                make_float2(acc[f][g][0] + b0, acc[f][g][1] + b1);
            *(float2*)&out[(size_t)(row + 8) * DIMc + col] =
                make_float2(acc[f][g][2] + b0, acc[f][g][3] + b1);
        }
    }
}

// ---------------------------------------------------------------------------
extern "C" void kernel_launch(void* const* d_in, const int* in_sizes, int n_in,
                              void* d_out, int out_size) {
    const float* x     = (const float*)d_in[0];  // [4,1024,512]
    const float* w_qkv = (const float*)d_in[1];  // [512,1536]
    const float* w_out = (const float*)d_in[2];  // [512,512]
    const float* b_out = (const float*)d_in[3];  // [512]
    float* out = (float*)d_out;                  // [4,1024,512]

    k_qkv<<<dim3(QKV3c / 128, (Bc * Nc) / 128), 256>>>(x, w_qkv);
    k_dots<<<dim3(Nc / 128, Nc / 128, BHc), 256>>>();
    k_topk<<<(BHc * Nc) / 8, 256>>>();
    k_av<<<dim3(Nc / 128, BHc), 256>>>();
    k_out<<<dim3(DIMc / 128, (Bc * Nc) / 128), 256>>>(w_out, b_out, out);
}

// round 8
// speedup vs baseline: 3.1053x; 1.1276x over previous
#include <cuda_runtime.h>
#include <cuda_fp16.h>
#include <cstdint>

#define Bc     4
#define Nc     1024
#define Hc     8
#define Dc     64
#define DIMc   512
#define INNERc 512
#define QKV3c  1536
#define BHc    32
#define KKc    716
#define SCALEc 0.125f

// Scratch (device globals: no allocations allowed)
__device__ __half g_xh[Bc * Nc * DIMc], g_xl[Bc * Nc * DIMc];      // x split
__device__ __half g_wqh[QKV3c * DIMc], g_wql[QKV3c * DIMc];        // w_qkv^T split [n][k]
__device__ __half g_wo[DIMc * INNERc];                             // w_out^T fp16 [n][k]
__device__ __half g_qh[Bc * Nc * INNERc], g_ql[Bc * Nc * INNERc];  // Q*scale split
__device__ __half g_kh[Bc * Nc * INNERc], g_kl[Bc * Nc * INNERc];  // K split
__device__ __half g_vt[(size_t)BHc * Dc * Nc];                     // V^T [bh][d][n]
__device__ float  g_dots[(size_t)BHc * Nc * Nc];                   // fp32 pre-softmax
__device__ __half g_p[(size_t)BHc * Nc * Nc];                      // fp16 post-softmax
__device__ __half g_att[Bc * Nc * INNERc];                         // fp16

// ---------------------------------------------------------------------------
// helpers
// ---------------------------------------------------------------------------
__device__ __forceinline__ void split_h(float v, __half& hi, __half& lo) {
    __half h = __float2half_rn(v);
    hi = h;
    lo = __float2half_rn(v - __half2float(h));
}
__device__ __forceinline__ void mma16(float* c, const unsigned* a,
                                      unsigned b0, unsigned b1) {
    asm volatile(
        "mma.sync.aligned.m16n8k16.row.col.f32.f16.f16.f32 "
        "{%0,%1,%2,%3}, {%4,%5,%6,%7}, {%8,%9}, {%0,%1,%2,%3};"
        : "+f"(c[0]), "+f"(c[1]), "+f"(c[2]), "+f"(c[3])
        : "r"(a[0]), "r"(a[1]), "r"(a[2]), "r"(a[3]), "r"(b0), "r"(b1));
}
__device__ __forceinline__ unsigned f2o(float x) {
    unsigned u = __float_as_uint(x);
    return (u & 0x80000000u) ? ~u : (u | 0x80000000u);
}
__device__ __forceinline__ float o2f(unsigned u) {
    unsigned f = (u & 0x80000000u) ? (u & 0x7fffffffu) : ~u;
    return __uint_as_float(f);
}

// ---------------------------------------------------------------------------
// Prep kernels: split/convert inputs once
// ---------------------------------------------------------------------------
__global__ __launch_bounds__(256) void k_prep_x(const float* __restrict__ x) {
    int idx = blockIdx.x * 256 + threadIdx.x;       // 4-float groups
    float4 v = ((const float4*)x)[idx];
    float vv[4] = {v.x, v.y, v.z, v.w};
    __half hh[4], ll[4];
#pragma unroll
    for (int i = 0; i < 4; i++) split_h(vv[i], hh[i], ll[i]);
    ((uint2*)g_xh)[idx] = *(uint2*)hh;
    ((uint2*)g_xl)[idx] = *(uint2*)ll;
}

// w_qkv [512 k][1536 n] -> g_wqh/g_wql [n][k], tiled transpose
__global__ __launch_bounds__(256) void k_prep_wq(const float* __restrict__ w) {
    __shared__ float t[32][33];
    const int tx = threadIdx.x & 31, ty = threadIdx.x >> 5;
    const int n0 = blockIdx.x * 32, k0 = blockIdx.y * 32;
#pragma unroll
    for (int i = 0; i < 4; i++)
        t[ty + i * 8][tx] = w[(size_t)(k0 + ty + i * 8) * QKV3c + n0 + tx];
    __syncthreads();
#pragma unroll
    for (int i = 0; i < 4; i++) {
        int n = n0 + ty + i * 8;
        float v = t[tx][ty + i * 8];
        __half h, l;
        split_h(v, h, l);
        g_wqh[(size_t)n * DIMc + k0 + tx] = h;
        g_wql[(size_t)n * DIMc + k0 + tx] = l;
    }
}

// w_out [512 k][512 n] -> g_wo [n][k] fp16
__global__ __launch_bounds__(256) void k_prep_wo(const float* __restrict__ w) {
    __shared__ float t[32][33];
    const int tx = threadIdx.x & 31, ty = threadIdx.x >> 5;
    const int n0 = blockIdx.x * 32, k0 = blockIdx.y * 32;
#pragma unroll
    for (int i = 0; i < 4; i++)
        t[ty + i * 8][tx] = w[(size_t)(k0 + ty + i * 8) * DIMc + n0 + tx];
    __syncthreads();
#pragma unroll
    for (int i = 0; i < 4; i++) {
        int n = n0 + ty + i * 8;
        g_wo[(size_t)n * INNERc + k0 + tx] = __float2half(t[tx][ty + i * 8]);
    }
}

// ---------------------------------------------------------------------------
// Kernel 1: qkv GEMM, fp16-split (3 products), pure-copy mainloop.
// Epilogue routes: Q (scale, split), K (split), V (fp16, transposed).
// block 128x128, BK=32, 8 warps (2m x 4n), warp 64x32
// ---------------------------------------------------------------------------
__global__ __launch_bounds__(256) void k_qkv() {
    __shared__ __half Ah[128][40], Al[128][40];   // [m][k]
    __shared__ __half Bh[128][40], Bl[128][40];   // [n][k]
    const int tid = threadIdx.x, lane = tid & 31, wrp = tid >> 5;
    const int wm = wrp & 1, wn = wrp >> 1;
    const int tig = lane & 3, grp = lane >> 2;
    const int row0 = blockIdx.y * 128, col0 = blockIdx.x * 128;
    float acc[4][4][4] = {};

    for (int kt = 0; kt < DIMc; kt += 32) {
        __syncthreads();
#pragma unroll
        for (int it = 0; it < 2; it++) {
            int idx = tid + it * 256;
            int row = idx >> 2, q = idx & 3;
            size_t ga = (size_t)(row0 + row) * DIMc + kt + q * 8;
            *(int4*)&Ah[row][q * 8] = *(const int4*)&g_xh[ga];
            *(int4*)&Al[row][q * 8] = *(const int4*)&g_xl[ga];
            size_t gb = (size_t)(col0 + row) * DIMc + kt + q * 8;
            *(int4*)&Bh[row][q * 8] = *(const int4*)&g_wqh[gb];
            *(int4*)&Bl[row][q * 8] = *(const int4*)&g_wql[gb];
        }
        __syncthreads();

#pragma unroll
        for (int kk = 0; kk < 32; kk += 16) {
            unsigned ah[4][4], al[4][4];
#pragma unroll
            for (int f = 0; f < 4; f++) {
                int m = wm * 64 + f * 16 + grp;
                ah[f][0] = *(const unsigned*)&Ah[m][kk + tig * 2];
                ah[f][1] = *(const unsigned*)&Ah[m + 8][kk + tig * 2];
                ah[f][2] = *(const unsigned*)&Ah[m][kk + tig * 2 + 8];
                ah[f][3] = *(const unsigned*)&Ah[m + 8][kk + tig * 2 + 8];
                al[f][0] = *(const unsigned*)&Al[m][kk + tig * 2];
                al[f][1] = *(const unsigned*)&Al[m + 8][kk + tig * 2];
                al[f][2] = *(const unsigned*)&Al[m][kk + tig * 2 + 8];
                al[f][3] = *(const unsigned*)&Al[m + 8][kk + tig * 2 + 8];
            }
#pragma unroll
            for (int g = 0; g < 4; g++) {
                int n = wn * 32 + g * 8 + grp;
                unsigned bh0 = *(const unsigned*)&Bh[n][kk + tig * 2];
                unsigned bh1 = *(const unsigned*)&Bh[n][kk + tig * 2 + 8];
                unsigned bl0 = *(const unsigned*)&Bl[n][kk + tig * 2];
                unsigned bl1 = *(const unsigned*)&Bl[n][kk + tig * 2 + 8];
#pragma unroll
                for (int f = 0; f < 4; f++) {
                    mma16(acc[f][g], ah[f], bh0, bh1);
                    mma16(acc[f][g], ah[f], bl0, bl1);
                    mma16(acc[f][g], al[f], bh0, bh1);
                }
            }
        }
    }

    const int sec = blockIdx.x >> 2;            // 0=Q, 1=K, 2=V
    const int csec = (blockIdx.x & 3) * 128;    // column within section
#pragma unroll
    for (int f = 0; f < 4; f++) {
        int row = row0 + wm * 64 + f * 16 + grp;
#pragma unroll
        for (int g = 0; g < 4; g++) {
            int cl = csec + wn * 32 + g * 8 + tig * 2;
            if (sec == 0) {
                __half h0, l0, h1, l1, h2, l2, h3, l3;
                split_h(acc[f][g][0] * SCALEc, h0, l0);
                split_h(acc[f][g][1] * SCALEc, h1, l1);
                split_h(acc[f][g][2] * SCALEc, h2, l2);
                split_h(acc[f][g][3] * SCALEc, h3, l3);
                *(__half2*)&g_qh[(size_t)row * INNERc + cl] = __halves2half2(h0, h1);
                *(__half2*)&g_ql[(size_t)row * INNERc + cl] = __halves2half2(l0, l1);
                *(__half2*)&g_qh[(size_t)(row + 8) * INNERc + cl] = __halves2half2(h2, h3);
                *(__half2*)&g_ql[(size_t)(row + 8) * INNERc + cl] = __halves2half2(l2, l3);
            } else if (sec == 1) {
                __half h0, l0, h1, l1, h2, l2, h3, l3;
                split_h(acc[f][g][0], h0, l0);
                split_h(acc[f][g][1], h1, l1);
                split_h(acc[f][g][2], h2, l2);
                split_h(acc[f][g][3], h3, l3);
                *(__half2*)&g_kh[(size_t)row * INNERc + cl] = __halves2half2(h0, h1);
                *(__half2*)&g_kl[(size_t)row * INNERc + cl] = __halves2half2(l0, l1);
                *(__half2*)&g_kh[(size_t)(row + 8) * INNERc + cl] = __halves2half2(h2, h3);
                *(__half2*)&g_kl[(size_t)(row + 8) * INNERc + cl] = __halves2half2(l2, l3);
            } else {
                int h = cl >> 6, d = cl & 63;
                int b = row >> 10, n = row & 1023;
                size_t base = ((size_t)(b * 8 + h) * 64 + d) * 1024 + n;
                g_vt[base]            = __float2half(acc[f][g][0]);
                g_vt[base + 1024]     = __float2half(acc[f][g][1]);
                g_vt[base + 8]        = __float2half(acc[f][g][2]);
                g_vt[base + 1024 + 8] = __float2half(acc[f][g][3]);
            }
        }
    }
}

// ---------------------------------------------------------------------------
// Kernel 2: dots = (Q*scale) @ K^T, fp16-split, pure-copy mainloop
// block 128x128, D=64 in 2 BK=32 iters
// ---------------------------------------------------------------------------
__global__ __launch_bounds__(256) void k_dots() {
    __shared__ __half Qh[128][40], Ql[128][40];
    __shared__ __half Kh[128][40], Kl[128][40];
    const int tid = threadIdx.x, lane = tid & 31, wrp = tid >> 5;
    const int wm = wrp & 1, wn = wrp >> 1;
    const int tig = lane & 3, grp = lane >> 2;
    const int bh = blockIdx.z, b = bh >> 3, h = bh & 7;
    const int i0 = blockIdx.y * 128, j0 = blockIdx.x * 128;
    const size_t qrow0 = (size_t)(b * Nc + i0);
    const size_t krow0 = (size_t)(b * Nc + j0);
    float acc[4][4][4] = {};

    for (int kt = 0; kt < Dc; kt += 32) {
        __syncthreads();
#pragma unroll
        for (int it = 0; it < 2; it++) {
            int idx = tid + it * 256;
            int row = idx >> 2, q = idx & 3;
            size_t ga = (qrow0 + row) * INNERc + h * Dc + kt + q * 8;
            *(int4*)&Qh[row][q * 8] = *(const int4*)&g_qh[ga];
            *(int4*)&Ql[row][q * 8] = *(const int4*)&g_ql[ga];
            size_t gb = (krow0 + row) * INNERc + h * Dc + kt + q * 8;
            *(int4*)&Kh[row][q * 8] = *(const int4*)&g_kh[gb];
            *(int4*)&Kl[row][q * 8] = *(const int4*)&g_kl[gb];
        }
        __syncthreads();

#pragma unroll
        for (int kk = 0; kk < 32; kk += 16) {
            unsigned ah[4][4], al[4][4];
#pragma unroll
            for (int f = 0; f < 4; f++) {
                int m = wm * 64 + f * 16 + grp;
                ah[f][0] = *(const unsigned*)&Qh[m][kk + tig * 2];
                ah[f][1] = *(const unsigned*)&Qh[m + 8][kk + tig * 2];
                ah[f][2] = *(const unsigned*)&Qh[m][kk + tig * 2 + 8];
                ah[f][3] = *(const unsigned*)&Qh[m + 8][kk + tig * 2 + 8];
                al[f][0] = *(const unsigned*)&Ql[m][kk + tig * 2];
                al[f][1] = *(const unsigned*)&Ql[m + 8][kk + tig * 2];
                al[f][2] = *(const unsigned*)&Ql[m][kk + tig * 2 + 8];
                al[f][3] = *(const unsigned*)&Ql[m + 8][kk + tig * 2 + 8];
            }
#pragma unroll
            for (int g = 0; g < 4; g++) {
                int n = wn * 32 + g * 8 + grp;
                unsigned bh0 = *(const unsigned*)&Kh[n][kk + tig * 2];
                unsigned bh1 = *(const unsigned*)&Kh[n][kk + tig * 2 + 8];
                unsigned bl0 = *(const unsigned*)&Kl[n][kk + tig * 2];
                unsigned bl1 = *(const unsigned*)&Kl[n][kk + tig * 2 + 8];
#pragma unroll
                for (int f = 0; f < 4; f++) {
                    mma16(acc[f][g], ah[f], bh0, bh1);
                    mma16(acc[f][g], ah[f], bl0, bl1);
                    mma16(acc[f][g], al[f], bh0, bh1);
                }
            }
        }
    }
    float* out = g_dots + (size_t)bh * Nc * Nc;
#pragma unroll
    for (int f = 0; f < 4; f++) {
        int row = i0 + wm * 64 + f * 16 + grp;
#pragma unroll
        for (int g = 0; g < 4; g++) {
            int col = j0 + wn * 32 + g * 8 + tig * 2;
            *(float2*)&out[(size_t)row * Nc + col] =
                make_float2(acc[f][g][0], acc[f][g][1]);
            *(float2*)&out[(size_t)(row + 8) * Nc + col] =
                make_float2(acc[f][g][2], acc[f][g][3]);
        }
    }
}

// ---------------------------------------------------------------------------
// Kernel 3: warp-per-row exact top-KK + masked softmax; 256-bin radix pass
// ---------------------------------------------------------------------------
__global__ __launch_bounds__(256) void k_topk() {
    __shared__ int      hist[8][256];
    __shared__ unsigned cand[8][32];
    __shared__ int      gc[8];

    const unsigned FULL = 0xffffffffu;
    const int tid = threadIdx.x, lane = tid & 31, w = tid >> 5;
    const size_t row = (size_t)blockIdx.x * 8 + w;
    const float* base = g_dots + row * Nc;
    __half* pb = g_p + row * Nc;

    unsigned u[32];
#pragma unroll
    for (int c = 0; c < 8; c++) {
        float4 v4 = *(const float4*)&base[c * 128 + lane * 4];
        u[c * 4 + 0] = f2o(v4.x);
        u[c * 4 + 1] = f2o(v4.y);
        u[c * 4 + 2] = f2o(v4.z);
        u[c * 4 + 3] = f2o(v4.w);
    }

    unsigned mn = u[0], mx = u[0];
#pragma unroll
    for (int i = 1; i < 32; i++) { mn = min(mn, u[i]); mx = max(mx, u[i]); }
#pragma unroll
    for (int o = 16; o; o >>= 1) {
        mn = min(mn, __shfl_xor_sync(FULL, mn, o));
        mx = max(mx, __shfl_xor_sync(FULL, mx, o));
    }

    unsigned long long lo = mn;
    unsigned long long range = (unsigned long long)mx - mn + 1ull;
    int r = Nc - KKc;   // 308
    unsigned thr = mn;

    for (int pass = 0; pass < 6; pass++) {
        if (range == 1ull) { thr = (unsigned)lo; break; }
#pragma unroll
        for (int j = 0; j < 8; j++) hist[w][j * 32 + lane] = 0;
        __syncwarp();
        const unsigned lo32 = (unsigned)lo;
        const unsigned hi32 = (unsigned)(lo + range - 1ull);
        const bool small = (range <= 256ull);
        const unsigned mul = small ? 0u : (unsigned)((256ull << 32) / range);
#pragma unroll
        for (int i = 0; i < 32; i++) {
            if (u[i] >= lo32 && u[i] <= hi32) {
                unsigned d = u[i] - lo32;
                int bin = small ? (int)d : (int)__umulhi(d, mul);
                atomicAdd(&hist[w][bin], 1);
            }
        }
        __syncwarp();
        int loc[8], s = 0;
#pragma unroll
        for (int j = 0; j < 8; j++) { loc[j] = hist[w][lane * 8 + j]; s += loc[j]; }
        int c = s;
#pragma unroll
        for (int o = 1; o < 32; o <<= 1) {
            int t = __shfl_up_sync(FULL, c, o);
            if (lane >= o) c += t;
        }
        int excl = c - s;
        unsigned bal = __ballot_sync(FULL, c > r);
        int L = __ffs(bal) - 1;
        int bkt = 0, r2 = 0, cnt = 0;
        if (lane == L) {
            int a2 = excl;
#pragma unroll
            for (int j = 0; j < 8; j++) {
                if (a2 + loc[j] > r) { bkt = lane * 8 + j; r2 = r - a2; cnt = loc[j]; break; }
                a2 += loc[j];
            }
        }
        bkt = __shfl_sync(FULL, bkt, L);
        r2  = __shfl_sync(FULL, r2, L);
        cnt = __shfl_sync(FULL, cnt, L);

        unsigned long long nlo, nhi;
        if (small) {
            nlo = lo + (unsigned)bkt;
            nhi = nlo;
        } else {
            unsigned long long dl = (((unsigned long long)bkt << 32) + mul - 1ull) / mul;
            unsigned long long dh = ((((unsigned long long)(bkt + 1)) << 32) + mul - 1ull) / mul - 1ull;
            if (dh > range - 1ull) dh = range - 1ull;
            nlo = lo + dl;
            nhi = lo + dh;
        }

        if (cnt <= 32) {
            if (lane == 0) gc[w] = 0;
            __syncwarp();
            const unsigned glo = (unsigned)nlo, ghi = (unsigned)nhi;
#pragma unroll
            for (int i = 0; i < 32; i++) {
                if (u[i] >= glo && u[i] <= ghi) {
                    int p = atomicAdd(&gc[w], 1);
                    cand[w][p] = u[i];
                }
            }
            __syncwarp();
            unsigned tu = 0;
            int rk = -1;
            if (lane < cnt) {
                tu = cand[w][lane];
                rk = 0;
                for (int j = 0; j < cnt; j++) {
                    unsigned o2 = cand[w][j];
                    rk += (o2 < tu) || (o2 == tu && j < lane);
                }
            }
            unsigned who = __ballot_sync(FULL, rk == r2);
            thr = __shfl_sync(FULL, tu, __ffs(who) - 1);
            break;
        } else {
            lo = nlo;
            range = nhi - nlo + 1ull;
            r = r2;
        }
    }

    const float rmax = o2f(mx);
    float sum = 0.f;
    float e[32];
#pragma unroll
    for (int i = 0; i < 32; i++) {
        unsigned ui = u[i];
        float v = o2f(ui);
        e[i] = (ui >= thr) ? __expf(v - rmax) : 0.f;
        sum += e[i];
    }
#pragma unroll
    for (int o = 16; o; o >>= 1) sum += __shfl_xor_sync(FULL, sum, o);
    const float inv = 1.0f / sum;
#pragma unroll
    for (int c = 0; c < 8; c++) {
        __half2 h01 = __floats2half2_rn(e[c * 4 + 0] * inv, e[c * 4 + 1] * inv);
        __half2 h23 = __floats2half2_rn(e[c * 4 + 2] * inv, e[c * 4 + 3] * inv);
        uint2 pk;
        pk.x = *(unsigned*)&h01;
        pk.y = *(unsigned*)&h23;
        *(uint2*)&pb[c * 128 + lane * 4] = pk;
    }
}

// ---------------------------------------------------------------------------
// Kernel 4: att[bh] = P[bh] @ V[bh]  fp16 MMA, V pre-transposed (pure copy)
// ---------------------------------------------------------------------------
__global__ __launch_bounds__(256) void k_av() {
    __shared__ __half Ph[128][72];
    __shared__ __half Vt[64][72];
    const int tid = threadIdx.x, lane = tid & 31, wrp = tid >> 5;
    const int wm = wrp >> 1, wn = wrp & 1;
    const int tig = lane & 3, grp = lane >> 2;
    const int bh = blockIdx.y, b = bh >> 3, h = bh & 7;
    const int i0 = blockIdx.x * 128;
    const __half* pg = g_p + ((size_t)bh * Nc + i0) * Nc;
    const __half* vt = g_vt + (size_t)bh * Dc * Nc;
    float acc[2][4][4] = {};

    for (int kc = 0; kc < Nc; kc += 64) {
        __syncthreads();
#pragma unroll
        for (int l = 0; l < 4; l++) {
            int idx = tid + l * 256;
            int row = idx >> 3, c8 = idx & 7;
            *(int4*)&Ph[row][c8 * 8] =
                *(const int4*)&pg[(size_t)row * Nc + kc + c8 * 8];
        }
#pragma unroll
        for (int l = 0; l < 2; l++) {
            int idx = tid + l * 256;
            int d = idx >> 3, c8 = idx & 7;
            *(int4*)&Vt[d][c8 * 8] =
                *(const int4*)&vt[(size_t)d * Nc + kc + c8 * 8];
        }
        __syncthreads();

#pragma unroll
        for (int kk = 0; kk < 64; kk += 16) {
            unsigned a[2][4];
#pragma unroll
            for (int f = 0; f < 2; f++) {
                int m = wm * 32 + f * 16 + grp;
                a[f][0] = *(const unsigned*)&Ph[m][kk + tig * 2];
                a[f][1] = *(const unsigned*)&Ph[m + 8][kk + tig * 2];
                a[f][2] = *(const unsigned*)&Ph[m][kk + tig * 2 + 8];
                a[f][3] = *(const unsigned*)&Ph[m + 8][kk + tig * 2 + 8];
            }
#pragma unroll
            for (int g = 0; g < 4; g++) {
                int n = wn * 32 + g * 8 + grp;
                unsigned b0 = *(const unsigned*)&Vt[n][kk + tig * 2];
                unsigned b1 = *(const unsigned*)&Vt[n][kk + tig * 2 + 8];
#pragma unroll
                for (int f = 0; f < 2; f++) mma16(acc[f][g], a[f], b0, b1);
            }
        }
    }
#pragma unroll
    for (int f = 0; f < 2; f++) {
        int rr = b * Nc + i0 + wm * 32 + f * 16 + grp;
#pragma unroll
        for (int g = 0; g < 4; g++) {
            int col = h * Dc + wn * 32 + g * 8 + tig * 2;
            __half2 h0 = __floats2half2_rn(acc[f][g][0], acc[f][g][1]);
            __half2 h1 = __floats2half2_rn(acc[f][g][2], acc[f][g][3]);
            *(__half2*)&g_att[rr * INNERc + col] = h0;
            *(__half2*)&g_att[(rr + 8) * INNERc + col] = h1;
        }
    }
}

// ---------------------------------------------------------------------------
// Kernel 5: out = att @ w_out + b_out, fp16 MMA, w pre-converted (pure copy)
// ---------------------------------------------------------------------------
__global__ __launch_bounds__(256) void k_out(const float* __restrict__ bias,
                                             float* __restrict__ out) {
    __shared__ __half Ah[128][72];
    __shared__ __half Bt[128][72];
    const int tid = threadIdx.x, lane = tid & 31, wrp = tid >> 5;
    const int wm = wrp & 1, wn = wrp >> 1;
    const int tig = lane & 3, grp = lane >> 2;
    const int row0 = blockIdx.y * 128, col0 = blockIdx.x * 128;
    float acc[4][4][4] = {};

    for (int kc = 0; kc < INNERc; kc += 64) {
        __syncthreads();
#pragma unroll
        for (int l = 0; l < 4; l++) {
            int idx = tid + l * 256;
            int row = idx >> 3, c8 = idx & 7;
            *(int4*)&Ah[row][c8 * 8] =
                *(const int4*)&g_att[(size_t)(row0 + row) * INNERc + kc + c8 * 8];
            *(int4*)&Bt[row][c8 * 8] =
                *(const int4*)&g_wo[(size_t)(col0 + row) * INNERc + kc + c8 * 8];
        }
        __syncthreads();

#pragma unroll
        for (int kk = 0; kk < 64; kk += 16) {
            unsigned a[4][4];
#pragma unroll
            for (int f = 0; f < 4; f++) {
                int m = wm * 64 + f * 16 + grp;
                a[f][0] = *(const unsigned*)&Ah[m][kk + tig * 2];
                a[f][1] = *(const unsigned*)&Ah[m + 8][kk + tig * 2];
                a[f][2] = *(const unsigned*)&Ah[m][kk + tig * 2 + 8];
                a[f][3] = *(const unsigned*)&Ah[m + 8][kk + tig * 2 + 8];
            }
#pragma unroll
            for (int g = 0; g < 4; g++) {
                int n = wn * 32 + g * 8 + grp;
                unsigned b0 = *(const unsigned*)&Bt[n][kk + tig * 2];
                unsigned b1 = *(const unsigned*)&Bt[n][kk + tig * 2 + 8];
#pragma unroll
                for (int f = 0; f < 4; f++) mma16(acc[f][g], a[f], b0, b1);
            }
        }
    }
#pragma unroll
    for (int f = 0; f < 4; f++) {
        int row = row0 + wm * 64 + f * 16 + grp;
#pragma unroll
        for (int g = 0; g < 4; g++) {
            int col = col0 + wn * 32 + g * 8 + tig * 2;
            float b0 = bias[col], b1 = bias[col + 1];
            *(float2*)&out[(size_t)row * DIMc + col] =
                make_float2(acc[f][g][0] + b0, acc[f][g][1] + b1);
            *(float2*)&out[(size_t)(row + 8) * DIMc + col] =
                make_float2(acc[f][g][2] + b0, acc[f][g][3] + b1);
        }
    }
}

// ---------------------------------------------------------------------------
extern "C" void kernel_launch(void* const* d_in, const int* in_sizes, int n_in,
                              void* d_out, int out_size) {
    const float* x     = (const float*)d_in[0];  // [4,1024,512]
    const float* w_qkv = (const float*)d_in[1];  // [512,1536]
    const float* w_out = (const float*)d_in[2];  // [512,512]
    const float* b_out = (const float*)d_in[3];  // [512]
    float* out = (float*)d_out;                  // [4,1024,512]

    k_prep_x<<<(Bc * Nc * DIMc / 4) / 256, 256>>>(x);
    k_prep_wq<<<dim3(QKV3c / 32, DIMc / 32), 256>>>(w_qkv);
    k_prep_wo<<<dim3(DIMc / 32, INNERc / 32), 256>>>(w_out);
    k_qkv<<<dim3(QKV3c / 128, (Bc * Nc) / 128), 256>>>();
    k_dots<<<dim3(Nc / 128, Nc / 128, BHc), 256>>>();
    k_topk<<<(BHc * Nc) / 8, 256>>>();
    k_av<<<dim3(Nc / 128, BHc), 256>>>();
    k_out<<<dim3(DIMc / 128, (Bc * Nc) / 128), 256>>>(b_out, out);
}

// round 9
// speedup vs baseline: 3.5068x; 1.1293x over previous
#include <cuda_runtime.h>
#include <cuda_fp16.h>
#include <cstdint>

#define Bc     4
#define Nc     1024
#define Hc     8
#define Dc     64
#define DIMc   512
#define INNERc 512
#define QKV3c  1536
#define BHc    32
#define KKc    716
#define SCALEc 0.125f

// Scratch (device globals: no allocations allowed)
__device__ __half g_xh[Bc * Nc * DIMc], g_xl[Bc * Nc * DIMc];      // x split
__device__ __half g_wqh[QKV3c * DIMc], g_wql[QKV3c * DIMc];        // w_qkv^T split [n][k]
__device__ __half g_wo[DIMc * INNERc];                             // w_out^T fp16 [n][k]
__device__ __half g_qh[Bc * Nc * INNERc], g_ql[Bc * Nc * INNERc];  // Q*scale split
__device__ __half g_kh[Bc * Nc * INNERc], g_kl[Bc * Nc * INNERc];  // K split
__device__ __half g_vt[(size_t)BHc * Dc * Nc];                     // V^T [bh][d][n]
__device__ float  g_dots[(size_t)BHc * Nc * Nc];                   // fp32 pre-softmax
__device__ __half g_p[(size_t)BHc * Nc * Nc];                      // fp16 post-softmax
__device__ __half g_att[Bc * Nc * INNERc];                         // fp16

// ---------------------------------------------------------------------------
// helpers
// ---------------------------------------------------------------------------
__device__ __forceinline__ void split_h(float v, __half& hi, __half& lo) {
    __half h = __float2half_rn(v);
    hi = h;
    lo = __float2half_rn(v - __half2float(h));
}
__device__ __forceinline__ void mma16(float* c, const unsigned* a,
                                      unsigned b0, unsigned b1) {
    asm volatile(
        "mma.sync.aligned.m16n8k16.row.col.f32.f16.f16.f32 "
        "{%0,%1,%2,%3}, {%4,%5,%6,%7}, {%8,%9}, {%0,%1,%2,%3};"
        : "+f"(c[0]), "+f"(c[1]), "+f"(c[2]), "+f"(c[3])
        : "r"(a[0]), "r"(a[1]), "r"(a[2]), "r"(a[3]), "r"(b0), "r"(b1));
}
__device__ __forceinline__ unsigned f2o(float x) {
    unsigned u = __float_as_uint(x);
    return (u & 0x80000000u) ? ~u : (u | 0x80000000u);
}
__device__ __forceinline__ float o2f(unsigned u) {
    unsigned f = (u & 0x80000000u) ? (u & 0x7fffffffu) : ~u;
    return __uint_as_float(f);
}
__device__ __forceinline__ uint32_t s2u(const void* p) {
    uint32_t a;
    asm("{ .reg .u64 t; cvta.to.shared.u64 t, %1; cvt.u32.u64 %0, t; }"
        : "=r"(a) : "l"(p));
    return a;
}
#define CP16(sa, gp) \
    asm volatile("cp.async.cg.shared.global [%0], [%1], 16;" :: "r"(sa), "l"(gp))
#define CPCOMMIT() asm volatile("cp.async.commit_group;")
#define CPWAIT1()  asm volatile("cp.async.wait_group 1;")
#define CPWAIT0()  asm volatile("cp.async.wait_group 0;")
__device__ __forceinline__ void ldsm4(unsigned* r, uint32_t a) {
    asm volatile("ldmatrix.sync.aligned.m8n8.x4.shared.b16 {%0,%1,%2,%3}, [%4];"
                 : "=r"(r[0]), "=r"(r[1]), "=r"(r[2]), "=r"(r[3]) : "r"(a));
}

// ---------------------------------------------------------------------------
// Prep kernels: split/convert inputs once
// ---------------------------------------------------------------------------
__global__ __launch_bounds__(256) void k_prep_x(const float* __restrict__ x) {
    int idx = blockIdx.x * 256 + threadIdx.x;
    float4 v = ((const float4*)x)[idx];
    float vv[4] = {v.x, v.y, v.z, v.w};
    __half hh[4], ll[4];
#pragma unroll
    for (int i = 0; i < 4; i++) split_h(vv[i], hh[i], ll[i]);
    ((uint2*)g_xh)[idx] = *(uint2*)hh;
    ((uint2*)g_xl)[idx] = *(uint2*)ll;
}

__global__ __launch_bounds__(256) void k_prep_wq(const float* __restrict__ w) {
    __shared__ float t[32][33];
    const int tx = threadIdx.x & 31, ty = threadIdx.x >> 5;
    const int n0 = blockIdx.x * 32, k0 = blockIdx.y * 32;
#pragma unroll
    for (int i = 0; i < 4; i++)
        t[ty + i * 8][tx] = w[(size_t)(k0 + ty + i * 8) * QKV3c + n0 + tx];
    __syncthreads();
#pragma unroll
    for (int i = 0; i < 4; i++) {
        int n = n0 + ty + i * 8;
        float v = t[tx][ty + i * 8];
        __half h, l;
        split_h(v, h, l);
        g_wqh[(size_t)n * DIMc + k0 + tx] = h;
        g_wql[(size_t)n * DIMc + k0 + tx] = l;
    }
}

__global__ __launch_bounds__(256) void k_prep_wo(const float* __restrict__ w) {
    __shared__ float t[32][33];
    const int tx = threadIdx.x & 31, ty = threadIdx.x >> 5;
    const int n0 = blockIdx.x * 32, k0 = blockIdx.y * 32;
#pragma unroll
    for (int i = 0; i < 4; i++)
        t[ty + i * 8][tx] = w[(size_t)(k0 + ty + i * 8) * DIMc + n0 + tx];
    __syncthreads();
#pragma unroll
    for (int i = 0; i < 4; i++) {
        int n = n0 + ty + i * 8;
        g_wo[(size_t)n * INNERc + k0 + tx] = __float2half(t[tx][ty + i * 8]);
    }
}

// ---------------------------------------------------------------------------
// Kernel 1: qkv GEMM, fp16-split, cp.async 2-stage + ldmatrix
// block 128x128, BK=32, 8 warps (2m x 4n), warp 64x32
// ---------------------------------------------------------------------------
#define QK_ARR 10240      // 128 rows * 80 B
#define QK_STG (4 * QK_ARR)
#define QK_SMEM (2 * QK_STG)

__global__ __launch_bounds__(256) void k_qkv() {
    extern __shared__ char sm[];
    const uint32_t sb = s2u(sm);
    const int tid = threadIdx.x, lane = tid & 31, wrp = tid >> 5;
    const int wm = wrp & 1, wn = wrp >> 1;
    const int tig = lane & 3, grp = lane >> 2;
    const int row0 = blockIdx.y * 128, col0 = blockIdx.x * 128;
    float acc[4][4][4] = {};

    const int lrow = tid >> 2, lq = tid & 3;
    const uint32_t a_row = (lane & 7) + ((lane >> 3) & 1) * 8;
    const uint32_t a_kof = (lane >> 4) * 8;
    const uint32_t b_row = (lane & 7) + ((lane >= 16) ? 8 : 0);
    const uint32_t b_kof = ((lane >> 3) & 1) * 8;

    auto load_stage = [&](int c, int st) {
        const uint32_t s0 = sb + st * QK_STG;
        const int kt = c * 32;
#pragma unroll
        for (int it = 0; it < 2; it++) {
            int row = lrow + it * 64;
            uint32_t so = row * 80 + lq * 16;
            size_t ga = (size_t)(row0 + row) * DIMc + kt + lq * 8;
            CP16(s0 + so, g_xh + ga);
            CP16(s0 + QK_ARR + so, g_xl + ga);
            size_t gb = (size_t)(col0 + row) * DIMc + kt + lq * 8;
            CP16(s0 + 2 * QK_ARR + so, g_wqh + gb);
            CP16(s0 + 3 * QK_ARR + so, g_wql + gb);
        }
        CPCOMMIT();
    };
    load_stage(0, 0);
    load_stage(1, 1);

    for (int c = 0; c < 16; c++) {
        if (c < 15) { CPWAIT1(); } else { CPWAIT0(); }
        __syncthreads();
        const uint32_t s0 = sb + (c & 1) * QK_STG;
#pragma unroll
        for (int kk = 0; kk < 32; kk += 16) {
            unsigned ah[4][4], al[4][4];
#pragma unroll
            for (int f = 0; f < 4; f++) {
                uint32_t ra = s0 + (wm * 64 + f * 16 + a_row) * 80 + (kk + a_kof) * 2;
                ldsm4(ah[f], ra);
                ldsm4(al[f], ra + QK_ARR);
            }
            unsigned bh[2][4], bl[2][4];
#pragma unroll
            for (int gp = 0; gp < 2; gp++) {
                uint32_t rb = s0 + 2 * QK_ARR +
                              (wn * 32 + gp * 16 + b_row) * 80 + (kk + b_kof) * 2;
                ldsm4(bh[gp], rb);
                ldsm4(bl[gp], rb + QK_ARR);
            }
#pragma unroll
            for (int g = 0; g < 4; g++) {
                unsigned h0 = bh[g >> 1][(g & 1) * 2], h1 = bh[g >> 1][(g & 1) * 2 + 1];
                unsigned l0 = bl[g >> 1][(g & 1) * 2], l1 = bl[g >> 1][(g & 1) * 2 + 1];
#pragma unroll
                for (int f = 0; f < 4; f++) {
                    mma16(acc[f][g], ah[f], h0, h1);
                    mma16(acc[f][g], ah[f], l0, l1);
                    mma16(acc[f][g], al[f], h0, h1);
                }
            }
        }
        __syncthreads();
        if (c + 2 < 16) load_stage(c + 2, c & 1);
    }

    const int sec = blockIdx.x >> 2;            // 0=Q, 1=K, 2=V
    const int csec = (blockIdx.x & 3) * 128;
#pragma unroll
    for (int f = 0; f < 4; f++) {
        int row = row0 + wm * 64 + f * 16 + grp;
#pragma unroll
        for (int g = 0; g < 4; g++) {
            int cl = csec + wn * 32 + g * 8 + tig * 2;
            if (sec == 0) {
                __half h0, l0, h1, l1, h2, l2, h3, l3;
                split_h(acc[f][g][0] * SCALEc, h0, l0);
                split_h(acc[f][g][1] * SCALEc, h1, l1);
                split_h(acc[f][g][2] * SCALEc, h2, l2);
                split_h(acc[f][g][3] * SCALEc, h3, l3);
                *(__half2*)&g_qh[(size_t)row * INNERc + cl] = __halves2half2(h0, h1);
                *(__half2*)&g_ql[(size_t)row * INNERc + cl] = __halves2half2(l0, l1);
                *(__half2*)&g_qh[(size_t)(row + 8) * INNERc + cl] = __halves2half2(h2, h3);
                *(__half2*)&g_ql[(size_t)(row + 8) * INNERc + cl] = __halves2half2(l2, l3);
            } else if (sec == 1) {
                __half h0, l0, h1, l1, h2, l2, h3, l3;
                split_h(acc[f][g][0], h0, l0);
                split_h(acc[f][g][1], h1, l1);
                split_h(acc[f][g][2], h2, l2);
                split_h(acc[f][g][3], h3, l3);
                *(__half2*)&g_kh[(size_t)row * INNERc + cl] = __halves2half2(h0, h1);
                *(__half2*)&g_kl[(size_t)row * INNERc + cl] = __halves2half2(l0, l1);
                *(__half2*)&g_kh[(size_t)(row + 8) * INNERc + cl] = __halves2half2(h2, h3);
                *(__half2*)&g_kl[(size_t)(row + 8) * INNERc + cl] = __halves2half2(l2, l3);
            } else {
                int h = cl >> 6, d = cl & 63;
                int b = row >> 10, n = row & 1023;
                size_t base = ((size_t)(b * 8 + h) * 64 + d) * 1024 + n;
                g_vt[base]            = __float2half(acc[f][g][0]);
                g_vt[base + 1024]     = __float2half(acc[f][g][1]);
                g_vt[base + 8]        = __float2half(acc[f][g][2]);
                g_vt[base + 1024 + 8] = __float2half(acc[f][g][3]);
            }
        }
    }
}

// ---------------------------------------------------------------------------
// Kernel 2: dots = (Q*scale) @ K^T, fp16-split, cp.async + ldmatrix
// block 128x128, D=64 in 2 BK=32 stages
// ---------------------------------------------------------------------------
__global__ __launch_bounds__(256) void k_dots() {
    extern __shared__ char sm[];
    const uint32_t sb = s2u(sm);
    const int tid = threadIdx.x, lane = tid & 31, wrp = tid >> 5;
    const int wm = wrp & 1, wn = wrp >> 1;
    const int tig = lane & 3, grp = lane >> 2;
    const int bh_ = blockIdx.z, b = bh_ >> 3, h = bh_ & 7;
    const int i0 = blockIdx.y * 128, j0 = blockIdx.x * 128;
    float acc[4][4][4] = {};

    const int lrow = tid >> 2, lq = tid & 3;
    const uint32_t a_row = (lane & 7) + ((lane >> 3) & 1) * 8;
    const uint32_t a_kof = (lane >> 4) * 8;
    const uint32_t b_row = (lane & 7) + ((lane >= 16) ? 8 : 0);
    const uint32_t b_kof = ((lane >> 3) & 1) * 8;

    auto load_stage = [&](int c, int st) {
        const uint32_t s0 = sb + st * QK_STG;
        const int kt = c * 32;
#pragma unroll
        for (int it = 0; it < 2; it++) {
            int row = lrow + it * 64;
            uint32_t so = row * 80 + lq * 16;
            size_t ga = (size_t)(b * Nc + i0 + row) * INNERc + h * Dc + kt + lq * 8;
            CP16(s0 + so, g_qh + ga);
            CP16(s0 + QK_ARR + so, g_ql + ga);
            size_t gb = (size_t)(b * Nc + j0 + row) * INNERc + h * Dc + kt + lq * 8;
            CP16(s0 + 2 * QK_ARR + so, g_kh + gb);
            CP16(s0 + 3 * QK_ARR + so, g_kl + gb);
        }
        CPCOMMIT();
    };
    load_stage(0, 0);
    load_stage(1, 1);

    for (int c = 0; c < 2; c++) {
        if (c == 0) { CPWAIT1(); } else { CPWAIT0(); }
        __syncthreads();
        const uint32_t s0 = sb + c * QK_STG;
#pragma unroll
        for (int kk = 0; kk < 32; kk += 16) {
            unsigned ah[4][4], al[4][4];
#pragma unroll
            for (int f = 0; f < 4; f++) {
                uint32_t ra = s0 + (wm * 64 + f * 16 + a_row) * 80 + (kk + a_kof) * 2;
                ldsm4(ah[f], ra);
                ldsm4(al[f], ra + QK_ARR);
            }
            unsigned bh[2][4], bl[2][4];
#pragma unroll
            for (int gp = 0; gp < 2; gp++) {
                uint32_t rb = s0 + 2 * QK_ARR +
                              (wn * 32 + gp * 16 + b_row) * 80 + (kk + b_kof) * 2;
                ldsm4(bh[gp], rb);
                ldsm4(bl[gp], rb + QK_ARR);
            }
#pragma unroll
            for (int g = 0; g < 4; g++) {
                unsigned h0 = bh[g >> 1][(g & 1) * 2], h1 = bh[g >> 1][(g & 1) * 2 + 1];
                unsigned l0 = bl[g >> 1][(g & 1) * 2], l1 = bl[g >> 1][(g & 1) * 2 + 1];
#pragma unroll
                for (int f = 0; f < 4; f++) {
                    mma16(acc[f][g], ah[f], h0, h1);
                    mma16(acc[f][g], ah[f], l0, l1);
                    mma16(acc[f][g], al[f], h0, h1);
                }
            }
        }
        __syncthreads();
    }
    float* out = g_dots + (size_t)bh_ * Nc * Nc;
#pragma unroll
    for (int f = 0; f < 4; f++) {
        int row = i0 + wm * 64 + f * 16 + grp;
#pragma unroll
        for (int g = 0; g < 4; g++) {
            int col = j0 + wn * 32 + g * 8 + tig * 2;
            *(float2*)&out[(size_t)row * Nc + col] =
                make_float2(acc[f][g][0], acc[f][g][1]);
            *(float2*)&out[(size_t)(row + 8) * Nc + col] =
                make_float2(acc[f][g][2], acc[f][g][3]);
        }
    }
}

// ---------------------------------------------------------------------------
// Kernel 3: warp-per-row exact top-KK + masked softmax; 256-bin radix pass
// ---------------------------------------------------------------------------
__global__ __launch_bounds__(256) void k_topk() {
    __shared__ int      hist[8][256];
    __shared__ unsigned cand[8][32];
    __shared__ int      gc[8];

    const unsigned FULL = 0xffffffffu;
    const int tid = threadIdx.x, lane = tid & 31, w = tid >> 5;
    const size_t row = (size_t)blockIdx.x * 8 + w;
    const float* base = g_dots + row * Nc;
    __half* pb = g_p + row * Nc;

    unsigned u[32];
#pragma unroll
    for (int c = 0; c < 8; c++) {
        float4 v4 = *(const float4*)&base[c * 128 + lane * 4];
        u[c * 4 + 0] = f2o(v4.x);
        u[c * 4 + 1] = f2o(v4.y);
        u[c * 4 + 2] = f2o(v4.z);
        u[c * 4 + 3] = f2o(v4.w);
    }

    unsigned mn = u[0], mx = u[0];
#pragma unroll
    for (int i = 1; i < 32; i++) { mn = min(mn, u[i]); mx = max(mx, u[i]); }
#pragma unroll
    for (int o = 16; o; o >>= 1) {
        mn = min(mn, __shfl_xor_sync(FULL, mn, o));
        mx = max(mx, __shfl_xor_sync(FULL, mx, o));
    }

    unsigned long long lo = mn;
    unsigned long long range = (unsigned long long)mx - mn + 1ull;
    int r = Nc - KKc;   // 308
    unsigned thr = mn;

    for (int pass = 0; pass < 6; pass++) {
        if (range == 1ull) { thr = (unsigned)lo; break; }
#pragma unroll
        for (int j = 0; j < 8; j++) hist[w][j * 32 + lane] = 0;
        __syncwarp();
        const unsigned lo32 = (unsigned)lo;
        const unsigned hi32 = (unsigned)(lo + range - 1ull);
        const bool small = (range <= 256ull);
        const unsigned mul = small ? 0u : (unsigned)((256ull << 32) / range);
#pragma unroll
        for (int i = 0; i < 32; i++) {
            if (u[i] >= lo32 && u[i] <= hi32) {
                unsigned d = u[i] - lo32;
                int bin = small ? (int)d : (int)__umulhi(d, mul);
                atomicAdd(&hist[w][bin], 1);
            }
        }
        __syncwarp();
        int loc[8], s = 0;
#pragma unroll
        for (int j = 0; j < 8; j++) { loc[j] = hist[w][lane * 8 + j]; s += loc[j]; }
        int c = s;
#pragma unroll
        for (int o = 1; o < 32; o <<= 1) {
            int t = __shfl_up_sync(FULL, c, o);
            if (lane >= o) c += t;
        }
        int excl = c - s;
        unsigned bal = __ballot_sync(FULL, c > r);
        int L = __ffs(bal) - 1;
        int bkt = 0, r2 = 0, cnt = 0;
        if (lane == L) {
            int a2 = excl;
#pragma unroll
            for (int j = 0; j < 8; j++) {
                if (a2 + loc[j] > r) { bkt = lane * 8 + j; r2 = r - a2; cnt = loc[j]; break; }
                a2 += loc[j];
            }
        }
        bkt = __shfl_sync(FULL, bkt, L);
        r2  = __shfl_sync(FULL, r2, L);
        cnt = __shfl_sync(FULL, cnt, L);

        unsigned long long nlo, nhi;
        if (small) {
            nlo = lo + (unsigned)bkt;
            nhi = nlo;
        } else {
            unsigned long long dl = (((unsigned long long)bkt << 32) + mul - 1ull) / mul;
            unsigned long long dh = ((((unsigned long long)(bkt + 1)) << 32) + mul - 1ull) / mul - 1ull;
            if (dh > range - 1ull) dh = range - 1ull;
            nlo = lo + dl;
            nhi = lo + dh;
        }

        if (cnt <= 32) {
            if (lane == 0) gc[w] = 0;
            __syncwarp();
            const unsigned glo = (unsigned)nlo, ghi = (unsigned)nhi;
#pragma unroll
            for (int i = 0; i < 32; i++) {
                if (u[i] >= glo && u[i] <= ghi) {
                    int p = atomicAdd(&gc[w], 1);
                    cand[w][p] = u[i];
                }
            }
            __syncwarp();
            unsigned tu = 0;
            int rk = -1;
            if (lane < cnt) {
                tu = cand[w][lane];
                rk = 0;
                for (int j = 0; j < cnt; j++) {
                    unsigned o2 = cand[w][j];
                    rk += (o2 < tu) || (o2 == tu && j < lane);
                }
            }
            unsigned who = __ballot_sync(FULL, rk == r2);
            thr = __shfl_sync(FULL, tu, __ffs(who) - 1);
            break;
        } else {
            lo = nlo;
            range = nhi - nlo + 1ull;
            r = r2;
        }
    }

    const float rmax = o2f(mx);
    float sum = 0.f;
    float e[32];
#pragma unroll
    for (int i = 0; i < 32; i++) {
        unsigned ui = u[i];
        float v = o2f(ui);
        e[i] = (ui >= thr) ? __expf(v - rmax) : 0.f;
        sum += e[i];
    }
#pragma unroll
    for (int o = 16; o; o >>= 1) sum += __shfl_xor_sync(FULL, sum, o);
    const float inv = 1.0f / sum;
#pragma unroll
    for (int c = 0; c < 8; c++) {
        __half2 h01 = __floats2half2_rn(e[c * 4 + 0] * inv, e[c * 4 + 1] * inv);
        __half2 h23 = __floats2half2_rn(e[c * 4 + 2] * inv, e[c * 4 + 3] * inv);
        uint2 pk;
        pk.x = *(unsigned*)&h01;
        pk.y = *(unsigned*)&h23;
        *(uint2*)&pb[c * 128 + lane * 4] = pk;
    }
}

// ---------------------------------------------------------------------------
// Kernel 4: att = P @ V, fp16 MMA, cp.async + ldmatrix
// block 128m x 64n, BK=64, 8 warps (4m x 2n)
// ---------------------------------------------------------------------------
#define AV_P   18432      // Ph: 128 rows * 144 B
#define AV_STG (AV_P + 64 * 144)
#define AV_SMEM (2 * AV_STG)

__global__ __launch_bounds__(256) void k_av() {
    extern __shared__ char sm[];
    const uint32_t sb = s2u(sm);
    const int tid = threadIdx.x, lane = tid & 31, wrp = tid >> 5;
    const int wm = wrp >> 1, wn = wrp & 1;
    const int tig = lane & 3, grp = lane >> 2;
    const int bh_ = blockIdx.y, b = bh_ >> 3, h = bh_ & 7;
    const int i0 = blockIdx.x * 128;
    const __half* pg = g_p + ((size_t)bh_ * Nc + i0) * Nc;
    const __half* vt = g_vt + (size_t)bh_ * Dc * Nc;
    float acc[2][4][4] = {};

    const uint32_t a_row = (lane & 7) + ((lane >> 3) & 1) * 8;
    const uint32_t a_kof = (lane >> 4) * 8;
    const uint32_t b_row = (lane & 7) + ((lane >= 16) ? 8 : 0);
    const uint32_t b_kof = ((lane >> 3) & 1) * 8;

    auto load_stage = [&](int c, int st) {
        const uint32_t s0 = sb + st * AV_STG;
        const int kc = c * 64;
#pragma unroll
        for (int it = 0; it < 4; it++) {
            int idx = tid + it * 256;
            int row = idx >> 3, c8 = idx & 7;
            CP16(s0 + row * 144 + c8 * 16, pg + (size_t)row * Nc + kc + c8 * 8);
        }
#pragma unroll
        for (int it = 0; it < 2; it++) {
            int idx = tid + it * 256;
            int d = idx >> 3, c8 = idx & 7;
            CP16(s0 + AV_P + d * 144 + c8 * 16, vt + (size_t)d * Nc + kc + c8 * 8);
        }
        CPCOMMIT();
    };
    load_stage(0, 0);
    load_stage(1, 1);

    for (int c = 0; c < 16; c++) {
        if (c < 15) { CPWAIT1(); } else { CPWAIT0(); }
        __syncthreads();
        const uint32_t s0 = sb + (c & 1) * AV_STG;
#pragma unroll
        for (int kk = 0; kk < 64; kk += 16) {
            unsigned a[2][4];
#pragma unroll
            for (int f = 0; f < 2; f++) {
                uint32_t ra = s0 + (wm * 32 + f * 16 + a_row) * 144 + (kk + a_kof) * 2;
                ldsm4(a[f], ra);
            }
            unsigned bb[2][4];
#pragma unroll
            for (int gp = 0; gp < 2; gp++) {
                uint32_t rb = s0 + AV_P +
                              (wn * 32 + gp * 16 + b_row) * 144 + (kk + b_kof) * 2;
                ldsm4(bb[gp], rb);
            }
#pragma unroll
            for (int g = 0; g < 4; g++) {
                unsigned b0 = bb[g >> 1][(g & 1) * 2], b1 = bb[g >> 1][(g & 1) * 2 + 1];
#pragma unroll
                for (int f = 0; f < 2; f++) mma16(acc[f][g], a[f], b0, b1);
            }
        }
        __syncthreads();
        if (c + 2 < 16) load_stage(c + 2, c & 1);
    }
#pragma unroll
    for (int f = 0; f < 2; f++) {
        int rr = b * Nc + i0 + wm * 32 + f * 16 + grp;
#pragma unroll
        for (int g = 0; g < 4; g++) {
            int col = h * Dc + wn * 32 + g * 8 + tig * 2;
            __half2 h0 = __floats2half2_rn(acc[f][g][0], acc[f][g][1]);
            __half2 h1 = __floats2half2_rn(acc[f][g][2], acc[f][g][3]);
            *(__half2*)&g_att[rr * INNERc + col] = h0;
            *(__half2*)&g_att[(rr + 8) * INNERc + col] = h1;
        }
    }
}

// ---------------------------------------------------------------------------
// Kernel 5: out = att @ w_out + b_out, fp16 MMA, cp.async + ldmatrix
// block 128x128, BK=64, 8 warps (2m x 4n)
// ---------------------------------------------------------------------------
#define KO_A   18432
#define KO_STG (2 * KO_A)
#define KO_SMEM (2 * KO_STG)

__global__ __launch_bounds__(256) void k_out(const float* __restrict__ bias,
                                             float* __restrict__ out) {
    extern __shared__ char sm[];
    const uint32_t sb = s2u(sm);
    const int tid = threadIdx.x, lane = tid & 31, wrp = tid >> 5;
    const int wm = wrp & 1, wn = wrp >> 1;
    const int tig = lane & 3, grp = lane >> 2;
    const int row0 = blockIdx.y * 128, col0 = blockIdx.x * 128;
    float acc[4][4][4] = {};

    const uint32_t a_row = (lane & 7) + ((lane >> 3) & 1) * 8;
    const uint32_t a_kof = (lane >> 4) * 8;
    const uint32_t b_row = (lane & 7) + ((lane >= 16) ? 8 : 0);
    const uint32_t b_kof = ((lane >> 3) & 1) * 8;

    auto load_stage = [&](int c, int st) {
        const uint32_t s0 = sb + st * KO_STG;
        const int kc = c * 64;
#pragma unroll
        for (int it = 0; it < 4; it++) {
            int idx = tid + it * 256;
            int row = idx >> 3, c8 = idx & 7;
            CP16(s0 + row * 144 + c8 * 16,
                 g_att + (size_t)(row0 + row) * INNERc + kc + c8 * 8);
            CP16(s0 + KO_A + row * 144 + c8 * 16,
                 g_wo + (size_t)(col0 + row) * INNERc + kc + c8 * 8);
        }
        CPCOMMIT();
    };
    load_stage(0, 0);
    load_stage(1, 1);

    for (int c = 0; c < 8; c++) {
        if (c < 7) { CPWAIT1(); } else { CPWAIT0(); }
        __syncthreads();
        const uint32_t s0 = sb + (c & 1) * KO_STG;
#pragma unroll
        for (int kk = 0; kk < 64; kk += 16) {
            unsigned a[4][4];
#pragma unroll
            for (int f = 0; f < 4; f++) {
                uint32_t ra = s0 + (wm * 64 + f * 16 + a_row) * 144 + (kk + a_kof) * 2;
                ldsm4(a[f], ra);
            }
            unsigned bb[2][4];
#pragma unroll
            for (int gp = 0; gp < 2; gp++) {
                uint32_t rb = s0 + KO_A +
                              (wn * 32 + gp * 16 + b_row) * 144 + (kk + b_kof) * 2;
                ldsm4(bb[gp], rb);
            }
#pragma unroll
            for (int g = 0; g < 4; g++) {
                unsigned b0 = bb[g >> 1][(g & 1) * 2], b1 = bb[g >> 1][(g & 1) * 2 + 1];
#pragma unroll
                for (int f = 0; f < 4; f++) mma16(acc[f][g], a[f], b0, b1);
            }
        }
        __syncthreads();
        if (c + 2 < 8) load_stage(c + 2, c & 1);
    }
#pragma unroll
    for (int f = 0; f < 4; f++) {
        int row = row0 + wm * 64 + f * 16 + grp;
#pragma unroll
        for (int g = 0; g < 4; g++) {
            int col = col0 + wn * 32 + g * 8 + tig * 2;
            float b0 = bias[col], b1 = bias[col + 1];
            *(float2*)&out[(size_t)row * DIMc + col] =
                make_float2(acc[f][g][0] + b0, acc[f][g][1] + b1);
            *(float2*)&out[(size_t)(row + 8) * DIMc + col] =
                make_float2(acc[f][g][2] + b0, acc[f][g][3] + b1);
        }
    }
}

// ---------------------------------------------------------------------------
extern "C" void kernel_launch(void* const* d_in, const int* in_sizes, int n_in,
                              void* d_out, int out_size) {
    const float* x     = (const float*)d_in[0];  // [4,1024,512]
    const float* w_qkv = (const float*)d_in[1];  // [512,1536]
    const float* w_out = (const float*)d_in[2];  // [512,512]
    const float* b_out = (const float*)d_in[3];  // [512]
    float* out = (float*)d_out;                  // [4,1024,512]

    cudaFuncSetAttribute(k_qkv, cudaFuncAttributeMaxDynamicSharedMemorySize, QK_SMEM);
    cudaFuncSetAttribute(k_dots, cudaFuncAttributeMaxDynamicSharedMemorySize, QK_SMEM);
    cudaFuncSetAttribute(k_av, cudaFuncAttributeMaxDynamicSharedMemorySize, AV_SMEM);
    cudaFuncSetAttribute(k_out, cudaFuncAttributeMaxDynamicSharedMemorySize, KO_SMEM);

    k_prep_x<<<(Bc * Nc * DIMc / 4) / 256, 256>>>(x);
    k_prep_wq<<<dim3(QKV3c / 32, DIMc / 32), 256>>>(w_qkv);
    k_prep_wo<<<dim3(DIMc / 32, INNERc / 32), 256>>>(w_out);
    k_qkv<<<dim3(QKV3c / 128, (Bc * Nc) / 128), 256, QK_SMEM>>>();
    k_dots<<<dim3(Nc / 128, Nc / 128, BHc), 256, QK_SMEM>>>();
    k_topk<<<(BHc * Nc) / 8, 256>>>();
    k_av<<<dim3(Nc / 128, BHc), 256, AV_SMEM>>>();
    k_out<<<dim3(DIMc / 128, (Bc * Nc) / 128), 256, KO_SMEM>>>(b_out, out);
}

// round 10
// speedup vs baseline: 3.5073x; 1.0001x over previous
#include <cuda_runtime.h>
#include <cuda_fp16.h>
#include <cstdint>

#define Bc     4
#define Nc     1024
#define Hc     8
#define Dc     64
#define DIMc   512
#define INNERc 512
#define QKV3c  1536
#define BHc    32
#define KKc    716
#define SCALEc 0.125f

// Scratch (device globals: no allocations allowed)
__device__ __half g_xh[Bc * Nc * DIMc], g_xl[Bc * Nc * DIMc];      // x split
__device__ __half g_wqh[QKV3c * DIMc], g_wql[QKV3c * DIMc];        // w_qkv^T split [n][k]
__device__ __half g_wo[DIMc * INNERc];                             // w_out^T fp16 [n][k]
__device__ __half g_qh[Bc * Nc * INNERc], g_ql[Bc * Nc * INNERc];  // Q*scale split
__device__ __half g_kh[Bc * Nc * INNERc], g_kl[Bc * Nc * INNERc];  // K split
__device__ __half g_vt[(size_t)BHc * Dc * Nc];                     // V^T [bh][d][n]
__device__ float  g_dots[(size_t)BHc * Nc * Nc];                   // fp32 pre-softmax
__device__ __half g_p[(size_t)BHc * Nc * Nc];                      // fp16 post-softmax
__device__ __half g_att[Bc * Nc * INNERc];                         // fp16

// ---------------------------------------------------------------------------
// helpers
// ---------------------------------------------------------------------------
__device__ __forceinline__ void split_h(float v, __half& hi, __half& lo) {
    __half h = __float2half_rn(v);
    hi = h;
    lo = __float2half_rn(v - __half2float(h));
}
__device__ __forceinline__ void mma16(float* c, const unsigned* a,
                                      unsigned b0, unsigned b1) {
    asm volatile(
        "mma.sync.aligned.m16n8k16.row.col.f32.f16.f16.f32 "
        "{%0,%1,%2,%3}, {%4,%5,%6,%7}, {%8,%9}, {%0,%1,%2,%3};"
        : "+f"(c[0]), "+f"(c[1]), "+f"(c[2]), "+f"(c[3])
        : "r"(a[0]), "r"(a[1]), "r"(a[2]), "r"(a[3]), "r"(b0), "r"(b1));
}
__device__ __forceinline__ unsigned f2o(float x) {
    unsigned u = __float_as_uint(x);
    return (u & 0x80000000u) ? ~u : (u | 0x80000000u);
}
__device__ __forceinline__ float o2f(unsigned u) {
    unsigned f = (u & 0x80000000u) ? (u & 0x7fffffffu) : ~u;
    return __uint_as_float(f);
}
__device__ __forceinline__ uint32_t s2u(const void* p) {
    uint32_t a;
    asm("{ .reg .u64 t; cvta.to.shared.u64 t, %1; cvt.u32.u64 %0, t; }"
        : "=r"(a) : "l"(p));
    return a;
}
#define CP16(sa, gp) \
    asm volatile("cp.async.cg.shared.global [%0], [%1], 16;" :: "r"(sa), "l"(gp))
#define CPCOMMIT() asm volatile("cp.async.commit_group;")
#define CPWAIT1()  asm volatile("cp.async.wait_group 1;")
#define CPWAIT0()  asm volatile("cp.async.wait_group 0;")
__device__ __forceinline__ void ldsm4(unsigned* r, uint32_t a) {
    asm volatile("ldmatrix.sync.aligned.m8n8.x4.shared.b16 {%0,%1,%2,%3}, [%4];"
                 : "=r"(r[0]), "=r"(r[1]), "=r"(r[2]), "=r"(r[3]) : "r"(a));
}

// ---------------------------------------------------------------------------
// Prep kernels: split/convert inputs once
// ---------------------------------------------------------------------------
__global__ __launch_bounds__(256) void k_prep_x(const float* __restrict__ x) {
    int idx = blockIdx.x * 256 + threadIdx.x;
    float4 v = ((const float4*)x)[idx];
    float vv[4] = {v.x, v.y, v.z, v.w};
    __half hh[4], ll[4];
#pragma unroll
    for (int i = 0; i < 4; i++) split_h(vv[i], hh[i], ll[i]);
    ((uint2*)g_xh)[idx] = *(uint2*)hh;
    ((uint2*)g_xl)[idx] = *(uint2*)ll;
}

__global__ __launch_bounds__(256) void k_prep_wq(const float* __restrict__ w) {
    __shared__ float t[32][33];
    const int tx = threadIdx.x & 31, ty = threadIdx.x >> 5;
    const int n0 = blockIdx.x * 32, k0 = blockIdx.y * 32;
#pragma unroll
    for (int i = 0; i < 4; i++)
        t[ty + i * 8][tx] = w[(size_t)(k0 + ty + i * 8) * QKV3c + n0 + tx];
    __syncthreads();
#pragma unroll
    for (int i = 0; i < 4; i++) {
        int n = n0 + ty + i * 8;
        float v = t[tx][ty + i * 8];
        __half h, l;
        split_h(v, h, l);
        g_wqh[(size_t)n * DIMc + k0 + tx] = h;
        g_wql[(size_t)n * DIMc + k0 + tx] = l;
    }
}

__global__ __launch_bounds__(256) void k_prep_wo(const float* __restrict__ w) {
    __shared__ float t[32][33];
    const int tx = threadIdx.x & 31, ty = threadIdx.x >> 5;
    const int n0 = blockIdx.x * 32, k0 = blockIdx.y * 32;
#pragma unroll
    for (int i = 0; i < 4; i++)
        t[ty + i * 8][tx] = w[(size_t)(k0 + ty + i * 8) * DIMc + n0 + tx];
    __syncthreads();
#pragma unroll
    for (int i = 0; i < 4; i++) {
        int n = n0 + ty + i * 8;
        g_wo[(size_t)n * INNERc + k0 + tx] = __float2half(t[tx][ty + i * 8]);
    }
}

// ---------------------------------------------------------------------------
// Kernel 1: qkv GEMM, fp16-split, cp.async 2-stage + ldmatrix, 2 CTAs/SM
// block 128x128, BK=32, 8 warps (2m x 4n), warp 64x32
// ---------------------------------------------------------------------------
#define QK_ARR 10240      // 128 rows * 80 B
#define QK_STG (4 * QK_ARR)
#define QK_SMEM (2 * QK_STG)

__global__ __launch_bounds__(256, 2) void k_qkv() {
    extern __shared__ char sm[];
    const uint32_t sb = s2u(sm);
    const int tid = threadIdx.x, lane = tid & 31, wrp = tid >> 5;
    const int wm = wrp & 1, wn = wrp >> 1;
    const int tig = lane & 3, grp = lane >> 2;
    const int row0 = blockIdx.y * 128, col0 = blockIdx.x * 128;
    float acc[4][4][4] = {};

    const int lrow = tid >> 2, lq = tid & 3;
    const uint32_t a_row = (lane & 7) + ((lane >> 3) & 1) * 8;
    const uint32_t a_kof = (lane >> 4) * 8;
    const uint32_t b_row = (lane & 7) + ((lane >= 16) ? 8 : 0);
    const uint32_t b_kof = ((lane >> 3) & 1) * 8;

    auto load_stage = [&](int c, int st) {
        const uint32_t s0 = sb + st * QK_STG;
        const int kt = c * 32;
#pragma unroll
        for (int it = 0; it < 2; it++) {
            int row = lrow + it * 64;
            uint32_t so = row * 80 + lq * 16;
            size_t ga = (size_t)(row0 + row) * DIMc + kt + lq * 8;
            CP16(s0 + so, g_xh + ga);
            CP16(s0 + QK_ARR + so, g_xl + ga);
            size_t gb = (size_t)(col0 + row) * DIMc + kt + lq * 8;
            CP16(s0 + 2 * QK_ARR + so, g_wqh + gb);
            CP16(s0 + 3 * QK_ARR + so, g_wql + gb);
        }
        CPCOMMIT();
    };
    load_stage(0, 0);
    load_stage(1, 1);

    for (int c = 0; c < 16; c++) {
        if (c < 15) { CPWAIT1(); } else { CPWAIT0(); }
        __syncthreads();
        const uint32_t s0 = sb + (c & 1) * QK_STG;
#pragma unroll
        for (int kk = 0; kk < 32; kk += 16) {
            unsigned ah[4][4], al[4][4];
#pragma unroll
            for (int f = 0; f < 4; f++) {
                uint32_t ra = s0 + (wm * 64 + f * 16 + a_row) * 80 + (kk + a_kof) * 2;
                ldsm4(ah[f], ra);
                ldsm4(al[f], ra + QK_ARR);
            }
            unsigned bh[2][4], bl[2][4];
#pragma unroll
            for (int gp = 0; gp < 2; gp++) {
                uint32_t rb = s0 + 2 * QK_ARR +
                              (wn * 32 + gp * 16 + b_row) * 80 + (kk + b_kof) * 2;
                ldsm4(bh[gp], rb);
                ldsm4(bl[gp], rb + QK_ARR);
            }
#pragma unroll
            for (int g = 0; g < 4; g++) {
                unsigned h0 = bh[g >> 1][(g & 1) * 2], h1 = bh[g >> 1][(g & 1) * 2 + 1];
                unsigned l0 = bl[g >> 1][(g & 1) * 2], l1 = bl[g >> 1][(g & 1) * 2 + 1];
#pragma unroll
                for (int f = 0; f < 4; f++) {
                    mma16(acc[f][g], ah[f], h0, h1);
                    mma16(acc[f][g], ah[f], l0, l1);
                    mma16(acc[f][g], al[f], h0, h1);
                }
            }
        }
        __syncthreads();
        if (c + 2 < 16) load_stage(c + 2, c & 1);
    }

    const int sec = blockIdx.x >> 2;            // 0=Q, 1=K, 2=V
    const int csec = (blockIdx.x & 3) * 128;
#pragma unroll
    for (int f = 0; f < 4; f++) {
        int row = row0 + wm * 64 + f * 16 + grp;
#pragma unroll
        for (int g = 0; g < 4; g++) {
            int cl = csec + wn * 32 + g * 8 + tig * 2;
            if (sec == 0) {
                __half h0, l0, h1, l1, h2, l2, h3, l3;
                split_h(acc[f][g][0] * SCALEc, h0, l0);
                split_h(acc[f][g][1] * SCALEc, h1, l1);
                split_h(acc[f][g][2] * SCALEc, h2, l2);
                split_h(acc[f][g][3] * SCALEc, h3, l3);
                *(__half2*)&g_qh[(size_t)row * INNERc + cl] = __halves2half2(h0, h1);
                *(__half2*)&g_ql[(size_t)row * INNERc + cl] = __halves2half2(l0, l1);
                *(__half2*)&g_qh[(size_t)(row + 8) * INNERc + cl] = __halves2half2(h2, h3);
                *(__half2*)&g_ql[(size_t)(row + 8) * INNERc + cl] = __halves2half2(l2, l3);
            } else if (sec == 1) {
                __half h0, l0, h1, l1, h2, l2, h3, l3;
                split_h(acc[f][g][0], h0, l0);
                split_h(acc[f][g][1], h1, l1);
                split_h(acc[f][g][2], h2, l2);
                split_h(acc[f][g][3], h3, l3);
                *(__half2*)&g_kh[(size_t)row * INNERc + cl] = __halves2half2(h0, h1);
                *(__half2*)&g_kl[(size_t)row * INNERc + cl] = __halves2half2(l0, l1);
                *(__half2*)&g_kh[(size_t)(row + 8) * INNERc + cl] = __halves2half2(h2, h3);
                *(__half2*)&g_kl[(size_t)(row + 8) * INNERc + cl] = __halves2half2(l2, l3);
            } else {
                int h = cl >> 6, d = cl & 63;
                int b = row >> 10, n = row & 1023;
                size_t base = ((size_t)(b * 8 + h) * 64 + d) * 1024 + n;
                g_vt[base]            = __float2half(acc[f][g][0]);
                g_vt[base + 1024]     = __float2half(acc[f][g][1]);
                g_vt[base + 8]        = __float2half(acc[f][g][2]);
                g_vt[base + 1024 + 8] = __float2half(acc[f][g][3]);
            }
        }
    }
}

// ---------------------------------------------------------------------------
// Kernel 2: dots = (Q*scale) @ K^T, fp16-split, cp.async + ldmatrix, 2 CTAs/SM
// block 128x128, D=64 in 2 BK=32 stages
// ---------------------------------------------------------------------------
__global__ __launch_bounds__(256, 2) void k_dots() {
    extern __shared__ char sm[];
    const uint32_t sb = s2u(sm);
    const int tid = threadIdx.x, lane = tid & 31, wrp = tid >> 5;
    const int wm = wrp & 1, wn = wrp >> 1;
    const int tig = lane & 3, grp = lane >> 2;
    const int bh_ = blockIdx.z, b = bh_ >> 3, h = bh_ & 7;
    const int i0 = blockIdx.y * 128, j0 = blockIdx.x * 128;
    float acc[4][4][4] = {};

    const int lrow = tid >> 2, lq = tid & 3;
    const uint32_t a_row = (lane & 7) + ((lane >> 3) & 1) * 8;
    const uint32_t a_kof = (lane >> 4) * 8;
    const uint32_t b_row = (lane & 7) + ((lane >= 16) ? 8 : 0);
    const uint32_t b_kof = ((lane >> 3) & 1) * 8;

    auto load_stage = [&](int c, int st) {
        const uint32_t s0 = sb + st * QK_STG;
        const int kt = c * 32;
#pragma unroll
        for (int it = 0; it < 2; it++) {
            int row = lrow + it * 64;
            uint32_t so = row * 80 + lq * 16;
            size_t ga = (size_t)(b * Nc + i0 + row) * INNERc + h * Dc + kt + lq * 8;
            CP16(s0 + so, g_qh + ga);
            CP16(s0 + QK_ARR + so, g_ql + ga);
            size_t gb = (size_t)(b * Nc + j0 + row) * INNERc + h * Dc + kt + lq * 8;
            CP16(s0 + 2 * QK_ARR + so, g_kh + gb);
            CP16(s0 + 3 * QK_ARR + so, g_kl + gb);
        }
        CPCOMMIT();
    };
    load_stage(0, 0);
    load_stage(1, 1);

    for (int c = 0; c < 2; c++) {
        if (c == 0) { CPWAIT1(); } else { CPWAIT0(); }
        __syncthreads();
        const uint32_t s0 = sb + c * QK_STG;
#pragma unroll
        for (int kk = 0; kk < 32; kk += 16) {
            unsigned ah[4][4], al[4][4];
#pragma unroll
            for (int f = 0; f < 4; f++) {
                uint32_t ra = s0 + (wm * 64 + f * 16 + a_row) * 80 + (kk + a_kof) * 2;
                ldsm4(ah[f], ra);
                ldsm4(al[f], ra + QK_ARR);
            }
            unsigned bh[2][4], bl[2][4];
#pragma unroll
            for (int gp = 0; gp < 2; gp++) {
                uint32_t rb = s0 + 2 * QK_ARR +
                              (wn * 32 + gp * 16 + b_row) * 80 + (kk + b_kof) * 2;
                ldsm4(bh[gp], rb);
                ldsm4(bl[gp], rb + QK_ARR);
            }
#pragma unroll
            for (int g = 0; g < 4; g++) {
                unsigned h0 = bh[g >> 1][(g & 1) * 2], h1 = bh[g >> 1][(g & 1) * 2 + 1];
                unsigned l0 = bl[g >> 1][(g & 1) * 2], l1 = bl[g >> 1][(g & 1) * 2 + 1];
#pragma unroll
                for (int f = 0; f < 4; f++) {
                    mma16(acc[f][g], ah[f], h0, h1);
                    mma16(acc[f][g], ah[f], l0, l1);
                    mma16(acc[f][g], al[f], h0, h1);
                }
            }
        }
        __syncthreads();
    }
    float* out = g_dots + (size_t)bh_ * Nc * Nc;
#pragma unroll
    for (int f = 0; f < 4; f++) {
        int row = i0 + wm * 64 + f * 16 + grp;
#pragma unroll
        for (int g = 0; g < 4; g++) {
            int col = j0 + wn * 32 + g * 8 + tig * 2;
            *(float2*)&out[(size_t)row * Nc + col] =
                make_float2(acc[f][g][0], acc[f][g][1]);
            *(float2*)&out[(size_t)(row + 8) * Nc + col] =
                make_float2(acc[f][g][2], acc[f][g][3]);
        }
    }
}

// ---------------------------------------------------------------------------
// Kernel 3: warp-per-row exact top-KK + masked softmax; 256-bin radix pass
// ---------------------------------------------------------------------------
__global__ __launch_bounds__(256) void k_topk() {
    __shared__ int      hist[8][256];
    __shared__ unsigned cand[8][32];
    __shared__ int      gc[8];

    const unsigned FULL = 0xffffffffu;
    const int tid = threadIdx.x, lane = tid & 31, w = tid >> 5;
    const size_t row = (size_t)blockIdx.x * 8 + w;
    const float* base = g_dots + row * Nc;
    __half* pb = g_p + row * Nc;

    unsigned u[32];
#pragma unroll
    for (int c = 0; c < 8; c++) {
        float4 v4 = *(const float4*)&base[c * 128 + lane * 4];
        u[c * 4 + 0] = f2o(v4.x);
        u[c * 4 + 1] = f2o(v4.y);
        u[c * 4 + 2] = f2o(v4.z);
        u[c * 4 + 3] = f2o(v4.w);
    }

    unsigned mn = u[0], mx = u[0];
#pragma unroll
    for (int i = 1; i < 32; i++) { mn = min(mn, u[i]); mx = max(mx, u[i]); }
#pragma unroll
    for (int o = 16; o; o >>= 1) {
        mn = min(mn, __shfl_xor_sync(FULL, mn, o));
        mx = max(mx, __shfl_xor_sync(FULL, mx, o));
    }

    unsigned long long lo = mn;
    unsigned long long range = (unsigned long long)mx - mn + 1ull;
    int r = Nc - KKc;   // 308
    unsigned thr = mn;

    for (int pass = 0; pass < 6; pass++) {
        if (range == 1ull) { thr = (unsigned)lo; break; }
#pragma unroll
        for (int j = 0; j < 8; j++) hist[w][j * 32 + lane] = 0;
        __syncwarp();
        const unsigned lo32 = (unsigned)lo;
        const unsigned hi32 = (unsigned)(lo + range - 1ull);
        const bool small = (range <= 256ull);
        const unsigned mul = small ? 0u : (unsigned)((256ull << 32) / range);
#pragma unroll
        for (int i = 0; i < 32; i++) {
            if (u[i] >= lo32 && u[i] <= hi32) {
                unsigned d = u[i] - lo32;
                int bin = small ? (int)d : (int)__umulhi(d, mul);
                atomicAdd(&hist[w][bin], 1);
            }
        }
        __syncwarp();
        int loc[8], s = 0;
#pragma unroll
        for (int j = 0; j < 8; j++) { loc[j] = hist[w][lane * 8 + j]; s += loc[j]; }
        int c = s;
#pragma unroll
        for (int o = 1; o < 32; o <<= 1) {
            int t = __shfl_up_sync(FULL, c, o);
            if (lane >= o) c += t;
        }
        int excl = c - s;
        unsigned bal = __ballot_sync(FULL, c > r);
        int L = __ffs(bal) - 1;
        int bkt = 0, r2 = 0, cnt = 0;
        if (lane == L) {
            int a2 = excl;
#pragma unroll
            for (int j = 0; j < 8; j++) {
                if (a2 + loc[j] > r) { bkt = lane * 8 + j; r2 = r - a2; cnt = loc[j]; break; }
                a2 += loc[j];
            }
        }
        bkt = __shfl_sync(FULL, bkt, L);
        r2  = __shfl_sync(FULL, r2, L);
        cnt = __shfl_sync(FULL, cnt, L);

        unsigned long long nlo, nhi;
        if (small) {
            nlo = lo + (unsigned)bkt;
            nhi = nlo;
        } else {
            unsigned long long dl = (((unsigned long long)bkt << 32) + mul - 1ull) / mul;
            unsigned long long dh = ((((unsigned long long)(bkt + 1)) << 32) + mul - 1ull) / mul - 1ull;
            if (dh > range - 1ull) dh = range - 1ull;
            nlo = lo + dl;
            nhi = lo + dh;
        }

        if (cnt <= 32) {
            if (lane == 0) gc[w] = 0;
            __syncwarp();
            const unsigned glo = (unsigned)nlo, ghi = (unsigned)nhi;
#pragma unroll
            for (int i = 0; i < 32; i++) {
                if (u[i] >= glo && u[i] <= ghi) {
                    int p = atomicAdd(&gc[w], 1);
                    cand[w][p] = u[i];
                }
            }
            __syncwarp();
            unsigned tu = 0;
            int rk = -1;
            if (lane < cnt) {
                tu = cand[w][lane];
                rk = 0;
                for (int j = 0; j < cnt; j++) {
                    unsigned o2 = cand[w][j];
                    rk += (o2 < tu) || (o2 == tu && j < lane);
                }
            }
            unsigned who = __ballot_sync(FULL, rk == r2);
            thr = __shfl_sync(FULL, tu, __ffs(who) - 1);
            break;
        } else {
            lo = nlo;
            range = nhi - nlo + 1ull;
            r = r2;
        }
    }

    const float rmax = o2f(mx);
    float sum = 0.f;
    float e[32];
#pragma unroll
    for (int i = 0; i < 32; i++) {
        unsigned ui = u[i];
        float v = o2f(ui);
        e[i] = (ui >= thr) ? __expf(v - rmax) : 0.f;
        sum += e[i];
    }
#pragma unroll
    for (int o = 16; o; o >>= 1) sum += __shfl_xor_sync(FULL, sum, o);
    const float inv = 1.0f / sum;
#pragma unroll
    for (int c = 0; c < 8; c++) {
        __half2 h01 = __floats2half2_rn(e[c * 4 + 0] * inv, e[c * 4 + 1] * inv);
        __half2 h23 = __floats2half2_rn(e[c * 4 + 2] * inv, e[c * 4 + 3] * inv);
        uint2 pk;
        pk.x = *(unsigned*)&h01;
        pk.y = *(unsigned*)&h23;
        *(uint2*)&pb[c * 128 + lane * 4] = pk;
    }
}

// ---------------------------------------------------------------------------
// Kernel 4: att = P @ V, fp16 MMA, cp.async + ldmatrix, 2 CTAs/SM
// block 128m x 64n, BK=64, 8 warps (4m x 2n)
// ---------------------------------------------------------------------------
#define AV_P   18432      // Ph: 128 rows * 144 B
#define AV_STG (AV_P + 64 * 144)
#define AV_SMEM (2 * AV_STG)

__global__ __launch_bounds__(256, 2) void k_av() {
    extern __shared__ char sm[];
    const uint32_t sb = s2u(sm);
    const int tid = threadIdx.x, lane = tid & 31, wrp = tid >> 5;
    const int wm = wrp >> 1, wn = wrp & 1;
    const int tig = lane & 3, grp = lane >> 2;
    const int bh_ = blockIdx.y, b = bh_ >> 3, h = bh_ & 7;
    const int i0 = blockIdx.x * 128;
    const __half* pg = g_p + ((size_t)bh_ * Nc + i0) * Nc;
    const __half* vt = g_vt + (size_t)bh_ * Dc * Nc;
    float acc[2][4][4] = {};

    const uint32_t a_row = (lane & 7) + ((lane >> 3) & 1) * 8;
    const uint32_t a_kof = (lane >> 4) * 8;
    const uint32_t b_row = (lane & 7) + ((lane >= 16) ? 8 : 0);
    const uint32_t b_kof = ((lane >> 3) & 1) * 8;

    auto load_stage = [&](int c, int st) {
        const uint32_t s0 = sb + st * AV_STG;
        const int kc = c * 64;
#pragma unroll
        for (int it = 0; it < 4; it++) {
            int idx = tid + it * 256;
            int row = idx >> 3, c8 = idx & 7;
            CP16(s0 + row * 144 + c8 * 16, pg + (size_t)row * Nc + kc + c8 * 8);
        }
#pragma unroll
        for (int it = 0; it < 2; it++) {
            int idx = tid + it * 256;
            int d = idx >> 3, c8 = idx & 7;
            CP16(s0 + AV_P + d * 144 + c8 * 16, vt + (size_t)d * Nc + kc + c8 * 8);
        }
        CPCOMMIT();
    };
    load_stage(0, 0);
    load_stage(1, 1);

    for (int c = 0; c < 16; c++) {
        if (c < 15) { CPWAIT1(); } else { CPWAIT0(); }
        __syncthreads();
        const uint32_t s0 = sb + (c & 1) * AV_STG;
#pragma unroll
        for (int kk = 0; kk < 64; kk += 16) {
            unsigned a[2][4];
#pragma unroll
            for (int f = 0; f < 2; f++) {
                uint32_t ra = s0 + (wm * 32 + f * 16 + a_row) * 144 + (kk + a_kof) * 2;
                ldsm4(a[f], ra);
            }
            unsigned bb[2][4];
#pragma unroll
            for (int gp = 0; gp < 2; gp++) {
                uint32_t rb = s0 + AV_P +
                              (wn * 32 + gp * 16 + b_row) * 144 + (kk + b_kof) * 2;
                ldsm4(bb[gp], rb);
            }
#pragma unroll
            for (int g = 0; g < 4; g++) {
                unsigned b0 = bb[g >> 1][(g & 1) * 2], b1 = bb[g >> 1][(g & 1) * 2 + 1];
#pragma unroll
                for (int f = 0; f < 2; f++) mma16(acc[f][g], a[f], b0, b1);
            }
        }
        __syncthreads();
        if (c + 2 < 16) load_stage(c + 2, c & 1);
    }
#pragma unroll
    for (int f = 0; f < 2; f++) {
        int rr = b * Nc + i0 + wm * 32 + f * 16 + grp;
#pragma unroll
        for (int g = 0; g < 4; g++) {
            int col = h * Dc + wn * 32 + g * 8 + tig * 2;
            __half2 h0 = __floats2half2_rn(acc[f][g][0], acc[f][g][1]);
            __half2 h1 = __floats2half2_rn(acc[f][g][2], acc[f][g][3]);
            *(__half2*)&g_att[rr * INNERc + col] = h0;
            *(__half2*)&g_att[(rr + 8) * INNERc + col] = h1;
        }
    }
}

// ---------------------------------------------------------------------------
// Kernel 5: out = att @ w_out + b_out, fp16 MMA, cp.async + ldmatrix, 2 CTAs/SM
// block 128x128, BK=64, 8 warps (2m x 4n)
// ---------------------------------------------------------------------------
#define KO_A   18432
#define KO_STG (2 * KO_A)
#define KO_SMEM (2 * KO_STG)

__global__ __launch_bounds__(256, 2) void k_out(const float* __restrict__ bias,
                                                float* __restrict__ out) {
    extern __shared__ char sm[];
    const uint32_t sb = s2u(sm);
    const int tid = threadIdx.x, lane = tid & 31, wrp = tid >> 5;
    const int wm = wrp & 1, wn = wrp >> 1;
    const int tig = lane & 3, grp = lane >> 2;
    const int row0 = blockIdx.y * 128, col0 = blockIdx.x * 128;
    float acc[4][4][4] = {};

    const uint32_t a_row = (lane & 7) + ((lane >> 3) & 1) * 8;
    const uint32_t a_kof = (lane >> 4) * 8;
    const uint32_t b_row = (lane & 7) + ((lane >= 16) ? 8 : 0);
    const uint32_t b_kof = ((lane >> 3) & 1) * 8;

    auto load_stage = [&](int c, int st) {
        const uint32_t s0 = sb + st * KO_STG;
        const int kc = c * 64;
#pragma unroll
        for (int it = 0; it < 4; it++) {
            int idx = tid + it * 256;
            int row = idx >> 3, c8 = idx & 7;
            CP16(s0 + row * 144 + c8 * 16,
                 g_att + (size_t)(row0 + row) * INNERc + kc + c8 * 8);
            CP16(s0 + KO_A + row * 144 + c8 * 16,
                 g_wo + (size_t)(col0 + row) * INNERc + kc + c8 * 8);
        }
        CPCOMMIT();
    };
    load_stage(0, 0);
    load_stage(1, 1);

    for (int c = 0; c < 8; c++) {
        if (c < 7) { CPWAIT1(); } else { CPWAIT0(); }
        __syncthreads();
        const uint32_t s0 = sb + (c & 1) * KO_STG;
#pragma unroll
        for (int kk = 0; kk < 64; kk += 16) {
            unsigned a[4][4];
#pragma unroll
            for (int f = 0; f < 4; f++) {
                uint32_t ra = s0 + (wm * 64 + f * 16 + a_row) * 144 + (kk + a_kof) * 2;
                ldsm4(a[f], ra);
            }
            unsigned bb[2][4];
#pragma unroll
            for (int gp = 0; gp < 2; gp++) {
                uint32_t rb = s0 + KO_A +
                              (wn * 32 + gp * 16 + b_row) * 144 + (kk + b_kof) * 2;
                ldsm4(bb[gp], rb);
            }
#pragma unroll
            for (int g = 0; g < 4; g++) {
                unsigned b0 = bb[g >> 1][(g & 1) * 2], b1 = bb[g >> 1][(g & 1) * 2 + 1];
#pragma unroll
                for (int f = 0; f < 4; f++) mma16(acc[f][g], a[f], b0, b1);
            }
        }
        __syncthreads();
        if (c + 2 < 8) load_stage(c + 2, c & 1);
    }
#pragma unroll
    for (int f = 0; f < 4; f++) {
        int row = row0 + wm * 64 + f * 16 + grp;
#pragma unroll
        for (int g = 0; g < 4; g++) {
            int col = col0 + wn * 32 + g * 8 + tig * 2;
            float b0 = bias[col], b1 = bias[col + 1];
            *(float2*)&out[(size_t)row * DIMc + col] =
                make_float2(acc[f][g][0] + b0, acc[f][g][1] + b1);
            *(float2*)&out[(size_t)(row + 8) * DIMc + col] =
                make_float2(acc[f][g][2] + b0, acc[f][g][3] + b1);
        }
    }
}

// ---------------------------------------------------------------------------
extern "C" void kernel_launch(void* const* d_in, const int* in_sizes, int n_in,
                              void* d_out, int out_size) {
    const float* x     = (const float*)d_in[0];  // [4,1024,512]
    const float* w_qkv = (const float*)d_in[1];  // [512,1536]
    const float* w_out = (const float*)d_in[2];  // [512,512]
    const float* b_out = (const float*)d_in[3];  // [512]
    float* out = (float*)d_out;                  // [4,1024,512]

    cudaFuncSetAttribute(k_qkv, cudaFuncAttributeMaxDynamicSharedMemorySize, QK_SMEM);
    cudaFuncSetAttribute(k_dots, cudaFuncAttributeMaxDynamicSharedMemorySize, QK_SMEM);
    cudaFuncSetAttribute(k_av, cudaFuncAttributeMaxDynamicSharedMemorySize, AV_SMEM);
    cudaFuncSetAttribute(k_out, cudaFuncAttributeMaxDynamicSharedMemorySize, KO_SMEM);

    k_prep_x<<<(Bc * Nc * DIMc / 4) / 256, 256>>>(x);
    k_prep_wq<<<dim3(QKV3c / 32, DIMc / 32), 256>>>(w_qkv);
    k_prep_wo<<<dim3(DIMc / 32, INNERc / 32), 256>>>(w_out);
    k_qkv<<<dim3(QKV3c / 128, (Bc * Nc) / 128), 256, QK_SMEM>>>();
    k_dots<<<dim3(Nc / 128, Nc / 128, BHc), 256, QK_SMEM>>>();
    k_topk<<<(BHc * Nc) / 8, 256>>>();
    k_av<<<dim3(Nc / 128, BHc), 256, AV_SMEM>>>();
    k_out<<<dim3(DIMc / 128, (Bc * Nc) / 128), 256, KO_SMEM>>>(b_out, out);
}